// round 14
// baseline (speedup 1.0000x reference)
#include <cuda_runtime.h>
#include <cuda_fp16.h>
#include <stdint.h>

#define CUR   512
#define FULLL 1024
#define BSZ   8
#define DIMM  1024
#define NH    16
#define HD    64

// ---------------- scratch (device globals; allocation-free) ----------------
__device__ __half g_QU[BSZ*NH*CUR*HD], g_QV[BSZ*NH*CUR*HD];
__device__ __half g_K [BSZ*NH*FULLL*HD], g_V [BSZ*NH*FULLL*HD];
__device__ __half g_R [NH*FULLL*HD];
__device__ __half g_P [(size_t)BSZ*NH*CUR*FULLL];   // REL-SHIFTED: P_shift[a][j] = P[a][j+511-a], *CSCALE
// A operands
__device__ __half g_Xf[8192*1024];
__device__ __half g_Xc[4096*1024];
__device__ __half g_Xp[1024*1024];
__device__ __half g_AO[4096*1024];
// W^T operands
__device__ __half g_Wkv[2048*1024];
__device__ __half g_Wq [1024*1024];
__device__ __half g_Wr [1024*1024];
__device__ __half g_Wp [1024*1024];

#define CSCALE (0.125f * 1.44269504f)   // SCALE * log2(e), folded into QU and P

// ---------------- helpers ----------------
__device__ __forceinline__ uint32_t smem_u32(const void* p){
    uint32_t a; asm("{ .reg .u64 t; cvta.to.shared.u64 t, %1; cvt.u32.u64 %0, t; }":"=r"(a):"l"(p)); return a;
}
__device__ __forceinline__ void ldsm4(uint32_t* r, uint32_t addr){
    asm volatile("ldmatrix.sync.aligned.m8n8.x4.shared.b16 {%0,%1,%2,%3}, [%4];"
        : "=r"(r[0]),"=r"(r[1]),"=r"(r[2]),"=r"(r[3]) : "r"(addr));
}
__device__ __forceinline__ void ldsm4t(uint32_t* r, uint32_t addr){
    asm volatile("ldmatrix.sync.aligned.m8n8.x4.trans.shared.b16 {%0,%1,%2,%3}, [%4];"
        : "=r"(r[0]),"=r"(r[1]),"=r"(r[2]),"=r"(r[3]) : "r"(addr));
}
__device__ __forceinline__ void mma_fp16(float* c, const uint32_t* a, uint32_t b0, uint32_t b1){
    asm volatile("mma.sync.aligned.m16n8k16.row.col.f32.f16.f16.f32 "
        "{%0,%1,%2,%3}, {%4,%5,%6,%7}, {%8,%9}, {%0,%1,%2,%3};"
        : "+f"(c[0]),"+f"(c[1]),"+f"(c[2]),"+f"(c[3])
        : "r"(a[0]),"r"(a[1]),"r"(a[2]),"r"(a[3]), "r"(b0),"r"(b1));
}
__device__ __forceinline__ uint32_t pack_half2(float x, float y){
    __half2 h = __floats2half2_rn(x, y);
    return *(uint32_t*)&h;
}
__device__ __forceinline__ void cpasync16(uint32_t dst, const void* src){
    asm volatile("cp.async.cg.shared.global [%0], [%1], 16;" :: "r"(dst), "l"(src));
}

// ---------------- warp-MMA fp16 GEMM core (validated round 10) ----------------
#define TSTR 72
#define TILE_ELEMS (128*TSTR)
#define SM_BYTES (2*TILE_ELEMS*2)

__device__ __forceinline__ void load_tile_async(uint32_t dsm, const __half* src, int ld){
    const int tid = threadIdx.x;
    #pragma unroll
    for (int i = 0; i < 4; i++) {
        int s = tid + (i<<8);
        int row = s >> 3, cq = s & 7;
        cpasync16(dsm + (uint32_t)(row*TSTR + cq*8)*2, src + (size_t)row*ld + cq*8);
    }
}

__device__ __forceinline__ void gemm_compute(
    const __half* pA, const __half* pB, int K, float acc[4][4][4])
{
    extern __shared__ __half smb[];
    const uint32_t base = smem_u32(smb);
    const uint32_t bA = base, bB = base + TILE_ELEMS*2;

    const int lane = threadIdx.x & 31, wid = threadIdx.x >> 5;
    const int wm = wid >> 2, wn = wid & 3;
    const int g = lane >> 3, lr = lane & 7;

    const int arow = wm*64 + lr + (g & 1)*8;
    const int kcol = (g >> 1)*8;
    uint32_t aoff[4];
    #pragma unroll
    for (int mf = 0; mf < 4; mf++) aoff[mf] = (uint32_t)(((arow + mf*16)*TSTR + kcol)*2);
    const int brow = wn*32 + lr + (g & 1)*8;
    uint32_t boff[2];
    #pragma unroll
    for (int np = 0; np < 2; np++) boff[np] = (uint32_t)(((brow + np*16)*TSTR + kcol)*2);

    const int nchunk = K >> 6;
    for (int kc = 0; kc < nchunk; kc++) {
        const int k0 = kc << 6;
        __syncthreads();
        load_tile_async(bA, pA + k0, K);
        load_tile_async(bB, pB + k0, K);
        asm volatile("cp.async.commit_group;");
        asm volatile("cp.async.wait_group 0;" ::: "memory");
        __syncthreads();
        #pragma unroll
        for (int ks = 0; ks < 4; ks++) {
            const uint32_t kb = ks*32;
            uint32_t a4[4][4], bp[2][4];
            #pragma unroll
            for (int mf = 0; mf < 4; mf++) ldsm4(a4[mf], bA + aoff[mf] + kb);
            ldsm4(bp[0], bB + boff[0] + kb);
            ldsm4(bp[1], bB + boff[1] + kb);
            #pragma unroll
            for (int mf = 0; mf < 4; mf++)
                #pragma unroll
                for (int nf = 0; nf < 4; nf++)
                    mma_fp16(acc[mf][nf], a4[mf], bp[nf>>1][nf&1], bp[nf>>1][2+(nf&1)]);
        }
    }
}

// ---------------- merged projection GEMM (KV + Q + R in one launch) ----------------
__global__ __launch_bounds__(256, 2) void k_gemm_projs(
    const float* __restrict__ b_kv, const float* __restrict__ b_q,
    const float* __restrict__ b_pos,
    const float* __restrict__ u, const float* __restrict__ v)
{
    const int id = blockIdx.x;
    const int lane = threadIdx.x & 31, wid = threadIdx.x >> 5;
    float acc[4][4][4] = {};

    if (id < 1024) {
        // ---- KV ----
        const int m0 = (id >> 4)*128, n0 = (id & 15)*128;
        gemm_compute(g_Xf + (size_t)m0*DIMM, g_Wkv + (size_t)n0*DIMM, DIMM, acc);
        const int r0 = m0 + (wid>>2)*64 + (lane>>2);
        const int c0 = n0 + (wid&3)*32 + (lane&3)*2;
        #pragma unroll
        for (int nf = 0; nf < 4; nf++) {
            const int n = c0 + nf*8;
            const bool isK = n < 1024;
            const int nn = n & 1023, hh = nn >> 6, d = nn & 63;
            __half* D = isK ? g_K : g_V;
            const float2 bv = *(const float2*)(b_kv + n);
            #pragma unroll
            for (int mf = 0; mf < 4; mf++) {
                int m = r0 + mf*16;
                int f = m >> 3, b = m & 7;
                size_t o = (((size_t)(b*NH + hh)*FULLL) + f)*HD + d;
                *(uint32_t*)(D + o)      = pack_half2(acc[mf][nf][0] + bv.x, acc[mf][nf][1] + bv.y);
                *(uint32_t*)(D + o + HD) = pack_half2(acc[mf][nf][2] + bv.x, acc[mf][nf][3] + bv.y);
            }
        }
    } else if (id < 1280) {
        // ---- Q (QU pre-scaled by CSCALE) ----
        const int t = id - 1024;
        const int m0 = (t >> 3)*128, n0 = (t & 7)*128;
        gemm_compute(g_Xc + (size_t)m0*DIMM, g_Wq + (size_t)n0*DIMM, DIMM, acc);
        const int r0 = m0 + (wid>>2)*64 + (lane>>2);
        const int c0 = n0 + (wid&3)*32 + (lane&3)*2;
        #pragma unroll
        for (int nf = 0; nf < 4; nf++) {
            const int n = c0 + nf*8;
            const int hh = n >> 6, d = n & 63;
            const float2 bv = *(const float2*)(b_q + n);
            const float2 uv = *(const float2*)(u + n);
            const float2 vv = *(const float2*)(v + n);
            #pragma unroll
            for (int mf = 0; mf < 4; mf++) {
                int m = r0 + mf*16;
                int c = m >> 3, b = m & 7;
                size_t o = (((size_t)(b*NH + hh)*CUR) + c)*HD + d;
                float x0 = acc[mf][nf][0] + bv.x, x1 = acc[mf][nf][1] + bv.y;
                *(uint32_t*)(g_QU + o) = pack_half2((x0 + uv.x)*CSCALE, (x1 + uv.y)*CSCALE);
                *(uint32_t*)(g_QV + o) = pack_half2(x0 + vv.x, x1 + vv.y);
                float y0 = acc[mf][nf][2] + bv.x, y1 = acc[mf][nf][3] + bv.y;
                *(uint32_t*)(g_QU + o + HD) = pack_half2((y0 + uv.x)*CSCALE, (y1 + uv.y)*CSCALE);
                *(uint32_t*)(g_QV + o + HD) = pack_half2(y0 + vv.x, y1 + vv.y);
            }
        }
    } else {
        // ---- R ----
        const int t = id - 1280;
        const int m0 = (t >> 3)*128, n0 = (t & 7)*128;
        gemm_compute(g_Xp + (size_t)m0*DIMM, g_Wr + (size_t)n0*DIMM, DIMM, acc);
        const int r0 = m0 + (wid>>2)*64 + (lane>>2);
        const int c0 = n0 + (wid&3)*32 + (lane&3)*2;
        #pragma unroll
        for (int nf = 0; nf < 4; nf++) {
            const int n = c0 + nf*8;
            const int hh = n >> 6, d = n & 63;
            const float2 bv = *(const float2*)(b_pos + n);
            #pragma unroll
            for (int mf = 0; mf < 4; mf++) {
                int tt = r0 + mf*16;
                size_t o = ((size_t)hh*FULLL + tt)*HD + d;
                *(uint32_t*)(g_R + o)        = pack_half2(acc[mf][nf][0] + bv.x, acc[mf][nf][1] + bv.y);
                *(uint32_t*)(g_R + o + 8*HD) = pack_half2(acc[mf][nf][2] + bv.x, acc[mf][nf][3] + bv.y);
            }
        }
    }
}

// ---------------- P_shift[a][j] = (QV @ R^T)[a][j+511-a] * CSCALE, fp16 ----------------
__global__ __launch_bounds__(256, 2) void k_gemm_pos()
{
    const int m_blk = blockIdx.x, a_blk = blockIdx.y;
    if (a_blk + m_blk <= 2) return;   // all shifted columns negative: never read
    const int bh = blockIdx.z, hh = bh & 15;
    const int m0 = a_blk*128, n0 = m_blk*128;
    float acc[4][4][4] = {};
    gemm_compute(g_QV + ((size_t)bh*CUR + m0)*HD,
                 g_R  + ((size_t)hh*FULLL + n0)*HD, HD, acc);
    __half* Pp = g_P + (size_t)bh*CUR*FULLL;
    const int lane = threadIdx.x & 31, wid = threadIdx.x >> 5;
    const int r0 = m0 + (wid>>2)*64 + (lane>>2);
    const int c0 = n0 + (wid&3)*32 + (lane&3)*2;
    #pragma unroll
    for (int mf = 0; mf < 4; mf++) {
        const int ar = r0 + mf*16;
        #pragma unroll
        for (int nf = 0; nf < 4; nf++) {
            const int col = c0 + nf*8;
            int j  = col - 511 + ar;     // shifted column for rows ar / ar+8
            int j2 = j + 8;
            if ((unsigned)j      < 1024u) Pp[(size_t)ar*FULLL + j]          = __float2half_rn(acc[mf][nf][0]*CSCALE);
            if ((unsigned)(j+1)  < 1024u) Pp[(size_t)ar*FULLL + j + 1]      = __float2half_rn(acc[mf][nf][1]*CSCALE);
            if ((unsigned)j2     < 1024u) Pp[(size_t)(ar+8)*FULLL + j2]     = __float2half_rn(acc[mf][nf][2]*CSCALE);
            if ((unsigned)(j2+1) < 1024u) Pp[(size_t)(ar+8)*FULLL + j2 + 1] = __float2half_rn(acc[mf][nf][3]*CSCALE);
        }
    }
}

// ---------------- output projection ----------------
__global__ __launch_bounds__(256, 2) void k_gemm_proj(const float* __restrict__ bias,
                                                      float* __restrict__ out)
{
    const int m0 = blockIdx.y*128, n0 = blockIdx.x*128;
    float acc[4][4][4] = {};
    gemm_compute(g_AO + (size_t)m0*DIMM, g_Wp + (size_t)n0*DIMM, DIMM, acc);
    const int lane = threadIdx.x & 31, wid = threadIdx.x >> 5;
    const int r0 = m0 + (wid>>2)*64 + (lane>>2);
    const int c0 = n0 + (wid&3)*32 + (lane&3)*2;
    #pragma unroll
    for (int nf = 0; nf < 4; nf++) {
        const float2 bv = *(const float2*)(bias + c0 + nf*8);
        #pragma unroll
        for (int mf = 0; mf < 4; mf++) {
            float* p = out + (size_t)(r0 + mf*16)*DIMM + c0 + nf*8;
            *(float2*)p            = make_float2(acc[mf][nf][0] + bv.x, acc[mf][nf][1] + bv.y);
            *(float2*)(p + 8*DIMM) = make_float2(acc[mf][nf][2] + bv.x, acc[mf][nf][3] + bv.y);
        }
    }
}

// ---------------- single merged conversion kernel ----------------
#define NF_E (8192*1024)
#define NC_E (4096*1024)
#define NP_E (1024*1024)
#define NSPLIT_BLK ((NF_E + NC_E + NP_E)/1024)

__global__ __launch_bounds__(256) void k_convert(
    const float* __restrict__ full, const float* __restrict__ cur,
    const float* __restrict__ pos,
    const float* __restrict__ Wkv, const float* __restrict__ Wq,
    const float* __restrict__ Wpos, const float* __restrict__ Wproj)
{
    const int id = blockIdx.x;
    if (id < NSPLIT_BLK) {
        size_t i = ((size_t)id*256 + threadIdx.x) * 4;
        const float* src; __half* dst; size_t off;
        if (i < NF_E)             { src = full; dst = g_Xf; off = i; }
        else if (i < NF_E + NC_E) { src = cur;  dst = g_Xc; off = i - NF_E; }
        else                      { src = pos;  dst = g_Xp; off = i - NF_E - NC_E; }
        float4 vv = *(const float4*)(src + off);
        *(uint32_t*)(dst + off)     = pack_half2(vv.x, vv.y);
        *(uint32_t*)(dst + off + 2) = pack_half2(vv.z, vv.w);
    } else {
        __shared__ float t[32][33];
        const int tb = id - NSPLIT_BLK;
        const int x = tb % 160, y = tb / 160;
        const float* W; __half* wd; int N, n0;
        if (x < 64)       { W = Wkv;   wd = g_Wkv; N = 2048; n0 = x*32; }
        else if (x < 96)  { W = Wq;    wd = g_Wq;  N = 1024; n0 = (x-64)*32; }
        else if (x < 128) { W = Wpos;  wd = g_Wr;  N = 1024; n0 = (x-96)*32; }
        else              { W = Wproj; wd = g_Wp;  N = 1024; n0 = (x-128)*32; }
        const int k0 = y*32;
        const int tx = threadIdx.x & 31, ty = threadIdx.x >> 5;
        #pragma unroll
        for (int i = 0; i < 32; i += 8)
            t[ty+i][tx] = W[(size_t)(k0+ty+i)*N + n0+tx];
        __syncthreads();
        #pragma unroll
        for (int i = 0; i < 32; i += 8)
            wd[(size_t)(n0+ty+i)*DIMM + k0+tx] = __float2half_rn(t[tx][ty+i]);
    }
}

// ---------------- flash attention: pipelined K/V/P_shift, LDS-based P add ----------------
#define ARS 72
#define ATILE (64*ARS)                       // halves per K or V tile
#define PTILE (128*ARS)                      // halves per P_shift tile (128 rows x 64 cols + pad)
#define STAGE_H (2*ATILE + PTILE)            // 18432 halves per stage
#define AT_BYTES (2*STAGE_H*2)               // 73728 B, 2 CTAs/SM

__global__ __launch_bounds__(256, 2) void k_attn_mma()
{
    const int bh = blockIdx.y, b = bh >> 4, h = bh & 15;
    const int a0 = blockIdx.x * 128;
    extern __shared__ __half smh[];
    const uint32_t base = smem_u32(smh);

    const int tid = threadIdx.x, lane = tid & 31, w = tid >> 5;
    const int g = lane >> 2, q = lane & 3, qq2 = q*2;
    const int lr = lane & 7, gb = lane >> 3;
    const uint32_t lof = (uint32_t)((lr + (gb & 1)*8)*(ARS*2) + (gb >> 1)*16);

    const __half* Kp  = g_K + (size_t)bh*FULLL*HD;
    const __half* Vp  = g_V + (size_t)bh*FULLL*HD;
    const __half* Psh = g_P + (size_t)bh*CUR*FULLL;   // rel-shifted layout

    // ---- stage QU -> register A fragments (uses stage-1 buffer space) ----
    const __half* Qp = g_QU + ((size_t)bh*CUR + a0)*HD;
    uint32_t aQ[4][4];
    {
        __half* qbuf = smh + STAGE_H;
        #pragma unroll
        for (int i = 0; i < 4; i++) {
            int s = tid + (i<<8); int row = s >> 3, c = s & 7;
            *(float4*)(qbuf + row*ARS + c*8) = *(const float4*)(Qp + row*HD + c*8);
        }
        __syncthreads();
        const uint32_t bQ = base + STAGE_H*2;
        #pragma unroll
        for (int ks = 0; ks < 4; ks++) ldsm4(aQ[ks], bQ + (uint32_t)(w*16*ARS*2) + lof + ks*32);
        __syncthreads();
    }

    float oacc[8][4] = {};
    float rl0 = 0.f, rl1 = 0.f;
    const int arow0 = a0 + w*16 + g;
    const int amax = a0 + w*16 + 15;
    const int nkb = (a0 + 640) >> 6;
    const int prow0 = (w*16 + g)*ARS + qq2;      // P smem offset for rows g / g+8
    const int prow1 = prow0 + 8*ARS;

    auto issue = [&](int kb, int s){
        const int j0 = kb << 6;
        const uint32_t sb = base + (uint32_t)s*(STAGE_H*2);
        #pragma unroll
        for (int i = 0; i < 2; i++) {
            int t = tid + (i<<8); int row = t >> 3, c = t & 7;
            uint32_t off = (uint32_t)(row*ARS + c*8)*2;
            size_t gi = (size_t)(j0 + row)*HD + c*8;
            cpasync16(sb + off,           Kp + gi);
            cpasync16(sb + ATILE*2 + off, Vp + gi);
        }
        // P_shift tile: rows a0..a0+127, cols j0..j0+63
        #pragma unroll
        for (int i = 0; i < 4; i++) {
            int t = tid + (i<<8); int row = t >> 3, c8 = (t & 7)*8;
            cpasync16(sb + 2*ATILE*2 + (uint32_t)(row*ARS + c8)*2,
                      Psh + (size_t)(a0 + row)*FULLL + j0 + c8);
        }
        asm volatile("cp.async.commit_group;");
    };

    issue(0, 0);
    for (int kb = 0; kb < nkb; kb++) {
        const int j0 = kb << 6;
        if (kb + 1 < nkb) {
            issue(kb + 1, (kb + 1) & 1);
            asm volatile("cp.async.wait_group 1;" ::: "memory");
        } else {
            asm volatile("cp.async.wait_group 0;" ::: "memory");
        }
        __syncthreads();
        const uint32_t bK = base + (uint32_t)(kb & 1)*(STAGE_H*2);
        const uint32_t bV = bK + ATILE*2;
        const __half* sPb = smh + (size_t)(kb & 1)*STAGE_H + 2*ATILE;

        if (j0 <= amax + 512) {
            // ---- S = QU @ K^T (pre-scaled, log2 domain) ----
            float sacc[8][4] = {};
            #pragma unroll
            for (int n16 = 0; n16 < 4; n16++) {
                #pragma unroll
                for (int ks = 0; ks < 4; ks++) {
                    uint32_t k4[4];
                    ldsm4(k4, bK + (uint32_t)(n16*16*ARS*2) + lof + ks*32);
                    mma_fp16(sacc[2*n16],   aQ[ks], k4[0], k4[2]);
                    mma_fp16(sacc[2*n16+1], aQ[ks], k4[1], k4[3]);
                }
            }

            // ---- p = exp2(S + P_shift) with mask; accumulate raw row sums ----
            const int da = j0 - arow0;
            #pragma unroll
            for (int nf = 0; nf < 8; nf++) {
                __half2 pl0 = *(const __half2*)(sPb + prow0 + nf*8);
                __half2 pl1 = *(const __half2*)(sPb + prow1 + nf*8);
                const int e = da + nf*8 + qq2;   // j - arow0
                float p0 = (e     <= 512) ? exp2f(sacc[nf][0] + __low2float(pl0))  : 0.f;
                float p1 = (e + 1 <= 512) ? exp2f(sacc[nf][1] + __high2float(pl0)) : 0.f;
                float p2 = (e - 8 <= 512) ? exp2f(sacc[nf][2] + __low2float(pl1))  : 0.f;
                float p3 = (e - 7 <= 512) ? exp2f(sacc[nf][3] + __high2float(pl1)) : 0.f;
                sacc[nf][0] = p0; sacc[nf][1] = p1; sacc[nf][2] = p2; sacc[nf][3] = p3;
                rl0 += p0 + p1;
                rl1 += p2 + p3;
            }

            // ---- O += P~ @ V ----
            #pragma unroll
            for (int kf = 0; kf < 4; kf++) {
                uint32_t ap[4];
                ap[0] = pack_half2(sacc[2*kf][0],   sacc[2*kf][1]);
                ap[1] = pack_half2(sacc[2*kf][2],   sacc[2*kf][3]);
                ap[2] = pack_half2(sacc[2*kf+1][0], sacc[2*kf+1][1]);
                ap[3] = pack_half2(sacc[2*kf+1][2], sacc[2*kf+1][3]);
                #pragma unroll
                for (int d16 = 0; d16 < 4; d16++) {
                    uint32_t v4[4];
                    ldsm4t(v4, bV + (uint32_t)(kf*16*ARS*2) + lof + d16*32);
                    mma_fp16(oacc[2*d16],   ap, v4[0], v4[1]);
                    mma_fp16(oacc[2*d16+1], ap, v4[2], v4[3]);
                }
            }
        }
        __syncthreads();
    }

    // ---- finalize: single quad reduction, then divide ----
    rl0 += __shfl_xor_sync(0xffffffffu, rl0, 1);
    rl0 += __shfl_xor_sync(0xffffffffu, rl0, 2);
    rl1 += __shfl_xor_sync(0xffffffffu, rl1, 1);
    rl1 += __shfl_xor_sync(0xffffffffu, rl1, 2);
    float i0 = 1.f / rl0, i1 = 1.f / rl1;
    size_t base0 = ((size_t)arow0*BSZ + b)*(NH*HD) + h*HD;
    size_t base1 = ((size_t)(arow0+8)*BSZ + b)*(NH*HD) + h*HD;
    #pragma unroll
    for (int nf = 0; nf < 8; nf++) {
        int d = nf*8 + qq2;
        *(uint32_t*)(g_AO + base0 + d) = pack_half2(oacc[nf][0]*i0, oacc[nf][1]*i0);
        *(uint32_t*)(g_AO + base1 + d) = pack_half2(oacc[nf][2]*i1, oacc[nf][3]*i1);
    }
}

// ---------------- launch ----------------
extern "C" void kernel_launch(void* const* d_in, const int* in_sizes, int n_in,
                              void* d_out, int out_size)
{
    const float* inputs     = (const float*)d_in[0];
    const float* pos_emb    = (const float*)d_in[1];
    const float* full_input = (const float*)d_in[2];
    const float* u          = (const float*)d_in[3];
    const float* v          = (const float*)d_in[4];
    // d_in[5] = mask: unused (derived analytically)
    const float* W_kv   = (const float*)d_in[6];
    const float* b_kv   = (const float*)d_in[7];
    const float* W_q    = (const float*)d_in[8];
    const float* b_q    = (const float*)d_in[9];
    const float* W_pos  = (const float*)d_in[10];
    const float* b_pos  = (const float*)d_in[11];
    const float* W_proj = (const float*)d_in[12];
    const float* b_proj = (const float*)d_in[13];
    float* out = (float*)d_out;

    cudaFuncSetAttribute(k_attn_mma, cudaFuncAttributeMaxDynamicSharedMemorySize, AT_BYTES);

    // 1. all conversions in one launch
    k_convert<<<NSPLIT_BLK + 5120, 256>>>(full_input, inputs, pos_emb,
                                          W_kv, W_q, W_pos, W_proj);
    // 2. merged KV + Q + R projection GEMMs (QU pre-scaled)
    k_gemm_projs<<<1344, 256, SM_BYTES>>>(b_kv, b_q, b_pos, u, v);
    // 3. P_shift = rel-shifted (q+v) @ r^T * CSCALE, fp16, dead tiles skipped
    k_gemm_pos<<<dim3(8, 4, 128), 256, SM_BYTES>>>();
    // 4. attention (pipelined K/V/P_shift, smem P add)
    k_attn_mma<<<dim3(4, 128), 256, AT_BYTES>>>();
    // 5. output projection (fused bias)
    k_gemm_proj<<<dim3(8, 32), 256, SM_BYTES>>>(b_proj, out);
}

// round 15
// speedup vs baseline: 1.1704x; 1.1704x over previous
#include <cuda_runtime.h>
#include <cuda_fp16.h>
#include <stdint.h>

#define CUR   512
#define FULLL 1024
#define BSZ   8
#define DIMM  1024
#define NH    16
#define HD    64
#define PSTR  1088    // padded row stride of shifted-P (halves)

// ---------------- scratch (device globals; allocation-free) ----------------
__device__ __half g_QU[BSZ*NH*CUR*HD], g_QV[BSZ*NH*CUR*HD];
__device__ __half g_K [BSZ*NH*FULLL*HD], g_V [BSZ*NH*FULLL*HD];
__device__ __half g_R [NH*FULLL*HD];
// quantized-shift P: P[a][m]*CSCALE stored at column c = m - ((511-a)&~7)
__device__ __half g_P [(size_t)BSZ*NH*CUR*PSTR];
// A operands
__device__ __half g_Xf[8192*1024];
__device__ __half g_Xc[4096*1024];
__device__ __half g_Xp[1024*1024];
__device__ __half g_AO[4096*1024];
// W^T operands
__device__ __half g_Wkv[2048*1024];
__device__ __half g_Wq [1024*1024];
__device__ __half g_Wr [1024*1024];
__device__ __half g_Wp [1024*1024];

#define CSCALE (0.125f * 1.44269504f)

// ---------------- helpers ----------------
__device__ __forceinline__ uint32_t smem_u32(const void* p){
    uint32_t a; asm("{ .reg .u64 t; cvta.to.shared.u64 t, %1; cvt.u32.u64 %0, t; }":"=r"(a):"l"(p)); return a;
}
__device__ __forceinline__ void ldsm4(uint32_t* r, uint32_t addr){
    asm volatile("ldmatrix.sync.aligned.m8n8.x4.shared.b16 {%0,%1,%2,%3}, [%4];"
        : "=r"(r[0]),"=r"(r[1]),"=r"(r[2]),"=r"(r[3]) : "r"(addr));
}
__device__ __forceinline__ void ldsm4t(uint32_t* r, uint32_t addr){
    asm volatile("ldmatrix.sync.aligned.m8n8.x4.trans.shared.b16 {%0,%1,%2,%3}, [%4];"
        : "=r"(r[0]),"=r"(r[1]),"=r"(r[2]),"=r"(r[3]) : "r"(addr));
}
__device__ __forceinline__ void mma_fp16(float* c, const uint32_t* a, uint32_t b0, uint32_t b1){
    asm volatile("mma.sync.aligned.m16n8k16.row.col.f32.f16.f16.f32 "
        "{%0,%1,%2,%3}, {%4,%5,%6,%7}, {%8,%9}, {%0,%1,%2,%3};"
        : "+f"(c[0]),"+f"(c[1]),"+f"(c[2]),"+f"(c[3])
        : "r"(a[0]),"r"(a[1]),"r"(a[2]),"r"(a[3]), "r"(b0),"r"(b1));
}
__device__ __forceinline__ uint32_t pack_half2(float x, float y){
    __half2 h = __floats2half2_rn(x, y);
    return *(uint32_t*)&h;
}
__device__ __forceinline__ void cpasync16(uint32_t dst, const void* src){
    asm volatile("cp.async.cg.shared.global [%0], [%1], 16;" :: "r"(dst), "l"(src));
}

// ---------------- warp-MMA fp16 GEMM core (validated round 10) ----------------
#define TSTR 72
#define TILE_ELEMS (128*TSTR)
#define SM_BYTES (2*TILE_ELEMS*2)

__device__ __forceinline__ void load_tile_async(uint32_t dsm, const __half* src, int ld){
    const int tid = threadIdx.x;
    #pragma unroll
    for (int i = 0; i < 4; i++) {
        int s = tid + (i<<8);
        int row = s >> 3, cq = s & 7;
        cpasync16(dsm + (uint32_t)(row*TSTR + cq*8)*2, src + (size_t)row*ld + cq*8);
    }
}

__device__ __forceinline__ void gemm_compute(
    const __half* pA, const __half* pB, int K, float acc[4][4][4])
{
    extern __shared__ __half smb[];
    const uint32_t base = smem_u32(smb);
    const uint32_t bA = base, bB = base + TILE_ELEMS*2;

    const int lane = threadIdx.x & 31, wid = threadIdx.x >> 5;
    const int wm = wid >> 2, wn = wid & 3;
    const int g = lane >> 3, lr = lane & 7;

    const int arow = wm*64 + lr + (g & 1)*8;
    const int kcol = (g >> 1)*8;
    uint32_t aoff[4];
    #pragma unroll
    for (int mf = 0; mf < 4; mf++) aoff[mf] = (uint32_t)(((arow + mf*16)*TSTR + kcol)*2);
    const int brow = wn*32 + lr + (g & 1)*8;
    uint32_t boff[2];
    #pragma unroll
    for (int np = 0; np < 2; np++) boff[np] = (uint32_t)(((brow + np*16)*TSTR + kcol)*2);

    const int nchunk = K >> 6;
    for (int kc = 0; kc < nchunk; kc++) {
        const int k0 = kc << 6;
        __syncthreads();
        load_tile_async(bA, pA + k0, K);
        load_tile_async(bB, pB + k0, K);
        asm volatile("cp.async.commit_group;");
        asm volatile("cp.async.wait_group 0;" ::: "memory");
        __syncthreads();
        #pragma unroll
        for (int ks = 0; ks < 4; ks++) {
            const uint32_t kb = ks*32;
            uint32_t a4[4][4], bp[2][4];
            #pragma unroll
            for (int mf = 0; mf < 4; mf++) ldsm4(a4[mf], bA + aoff[mf] + kb);
            ldsm4(bp[0], bB + boff[0] + kb);
            ldsm4(bp[1], bB + boff[1] + kb);
            #pragma unroll
            for (int mf = 0; mf < 4; mf++)
                #pragma unroll
                for (int nf = 0; nf < 4; nf++)
                    mma_fp16(acc[mf][nf], a4[mf], bp[nf>>1][nf&1], bp[nf>>1][2+(nf&1)]);
        }
    }
}

// ---------------- merged projection GEMM (KV + Q + R in one launch) ----------------
__global__ __launch_bounds__(256, 2) void k_gemm_projs(
    const float* __restrict__ b_kv, const float* __restrict__ b_q,
    const float* __restrict__ b_pos,
    const float* __restrict__ u, const float* __restrict__ v)
{
    const int id = blockIdx.x;
    const int lane = threadIdx.x & 31, wid = threadIdx.x >> 5;
    float acc[4][4][4] = {};

    if (id < 1024) {
        const int m0 = (id >> 4)*128, n0 = (id & 15)*128;
        gemm_compute(g_Xf + (size_t)m0*DIMM, g_Wkv + (size_t)n0*DIMM, DIMM, acc);
        const int r0 = m0 + (wid>>2)*64 + (lane>>2);
        const int c0 = n0 + (wid&3)*32 + (lane&3)*2;
        #pragma unroll
        for (int nf = 0; nf < 4; nf++) {
            const int n = c0 + nf*8;
            const bool isK = n < 1024;
            const int nn = n & 1023, hh = nn >> 6, d = nn & 63;
            __half* D = isK ? g_K : g_V;
            const float2 bv = *(const float2*)(b_kv + n);
            #pragma unroll
            for (int mf = 0; mf < 4; mf++) {
                int m = r0 + mf*16;
                int f = m >> 3, b = m & 7;
                size_t o = (((size_t)(b*NH + hh)*FULLL) + f)*HD + d;
                *(uint32_t*)(D + o)      = pack_half2(acc[mf][nf][0] + bv.x, acc[mf][nf][1] + bv.y);
                *(uint32_t*)(D + o + HD) = pack_half2(acc[mf][nf][2] + bv.x, acc[mf][nf][3] + bv.y);
            }
        }
    } else if (id < 1280) {
        const int t = id - 1024;
        const int m0 = (t >> 3)*128, n0 = (t & 7)*128;
        gemm_compute(g_Xc + (size_t)m0*DIMM, g_Wq + (size_t)n0*DIMM, DIMM, acc);
        const int r0 = m0 + (wid>>2)*64 + (lane>>2);
        const int c0 = n0 + (wid&3)*32 + (lane&3)*2;
        #pragma unroll
        for (int nf = 0; nf < 4; nf++) {
            const int n = c0 + nf*8;
            const int hh = n >> 6, d = n & 63;
            const float2 bv = *(const float2*)(b_q + n);
            const float2 uv = *(const float2*)(u + n);
            const float2 vv = *(const float2*)(v + n);
            #pragma unroll
            for (int mf = 0; mf < 4; mf++) {
                int m = r0 + mf*16;
                int c = m >> 3, b = m & 7;
                size_t o = (((size_t)(b*NH + hh)*CUR) + c)*HD + d;
                float x0 = acc[mf][nf][0] + bv.x, x1 = acc[mf][nf][1] + bv.y;
                *(uint32_t*)(g_QU + o) = pack_half2((x0 + uv.x)*CSCALE, (x1 + uv.y)*CSCALE);
                *(uint32_t*)(g_QV + o) = pack_half2(x0 + vv.x, x1 + vv.y);
                float y0 = acc[mf][nf][2] + bv.x, y1 = acc[mf][nf][3] + bv.y;
                *(uint32_t*)(g_QU + o + HD) = pack_half2((y0 + uv.x)*CSCALE, (y1 + uv.y)*CSCALE);
                *(uint32_t*)(g_QV + o + HD) = pack_half2(y0 + vv.x, y1 + vv.y);
            }
        }
    } else {
        const int t = id - 1280;
        const int m0 = (t >> 3)*128, n0 = (t & 7)*128;
        gemm_compute(g_Xp + (size_t)m0*DIMM, g_Wr + (size_t)n0*DIMM, DIMM, acc);
        const int r0 = m0 + (wid>>2)*64 + (lane>>2);
        const int c0 = n0 + (wid&3)*32 + (lane&3)*2;
        #pragma unroll
        for (int nf = 0; nf < 4; nf++) {
            const int n = c0 + nf*8;
            const int hh = n >> 6, d = n & 63;
            const float2 bv = *(const float2*)(b_pos + n);
            #pragma unroll
            for (int mf = 0; mf < 4; mf++) {
                int tt = r0 + mf*16;
                size_t o = ((size_t)hh*FULLL + tt)*HD + d;
                *(uint32_t*)(g_R + o)        = pack_half2(acc[mf][nf][0] + bv.x, acc[mf][nf][1] + bv.y);
                *(uint32_t*)(g_R + o + 8*HD) = pack_half2(acc[mf][nf][2] + bv.x, acc[mf][nf][3] + bv.y);
            }
        }
    }
}

// ---------------- P quantized-shift store: P[a][m] -> column m - ((511-a)&~7) ----------------
__global__ __launch_bounds__(256, 2) void k_gemm_pos()
{
    const int m_blk = blockIdx.x, a_blk = blockIdx.y;
    if (a_blk + m_blk <= 2) return;   // never read
    const int bh = blockIdx.z, hh = bh & 15;
    const int m0 = a_blk*128, n0 = m_blk*128;
    float acc[4][4][4] = {};
    gemm_compute(g_QV + ((size_t)bh*CUR + m0)*HD,
                 g_R  + ((size_t)hh*FULLL + n0)*HD, HD, acc);
    __half* Pp = g_P + (size_t)bh*CUR*PSTR;
    const int lane = threadIdx.x & 31, wid = threadIdx.x >> 5;
    const int r0 = m0 + (wid>>2)*64 + (lane>>2);
    const int c0 = n0 + (wid&3)*32 + (lane&3)*2;
    #pragma unroll
    for (int mf = 0; mf < 4; mf++) {
        const int ar = r0 + mf*16;
        const int q1 = (511 - ar) & ~7;          // row ar
        const int q2 = (511 - ar - 8) & ~7;      // row ar+8
        #pragma unroll
        for (int nf = 0; nf < 4; nf++) {
            const int m = c0 + nf*8;             // even
            const int c1 = m - q1, c2 = m - q2;
            if ((unsigned)c1 < 1024u)
                *(uint32_t*)(Pp + (size_t)ar*PSTR + c1) =
                    pack_half2(acc[mf][nf][0]*CSCALE, acc[mf][nf][1]*CSCALE);
            if ((unsigned)c2 < 1024u)
                *(uint32_t*)(Pp + (size_t)(ar+8)*PSTR + c2) =
                    pack_half2(acc[mf][nf][2]*CSCALE, acc[mf][nf][3]*CSCALE);
        }
    }
}

// ---------------- output projection ----------------
__global__ __launch_bounds__(256, 2) void k_gemm_proj(const float* __restrict__ bias,
                                                      float* __restrict__ out)
{
    const int m0 = blockIdx.y*128, n0 = blockIdx.x*128;
    float acc[4][4][4] = {};
    gemm_compute(g_AO + (size_t)m0*DIMM, g_Wp + (size_t)n0*DIMM, DIMM, acc);
    const int lane = threadIdx.x & 31, wid = threadIdx.x >> 5;
    const int r0 = m0 + (wid>>2)*64 + (lane>>2);
    const int c0 = n0 + (wid&3)*32 + (lane&3)*2;
    #pragma unroll
    for (int nf = 0; nf < 4; nf++) {
        const float2 bv = *(const float2*)(bias + c0 + nf*8);
        #pragma unroll
        for (int mf = 0; mf < 4; mf++) {
            float* p = out + (size_t)(r0 + mf*16)*DIMM + c0 + nf*8;
            *(float2*)p            = make_float2(acc[mf][nf][0] + bv.x, acc[mf][nf][1] + bv.y);
            *(float2*)(p + 8*DIMM) = make_float2(acc[mf][nf][2] + bv.x, acc[mf][nf][3] + bv.y);
        }
    }
}

// ---------------- single merged conversion kernel ----------------
#define NF_E (8192*1024)
#define NC_E (4096*1024)
#define NP_E (1024*1024)
#define NSPLIT_BLK ((NF_E + NC_E + NP_E)/1024)

__global__ __launch_bounds__(256) void k_convert(
    const float* __restrict__ full, const float* __restrict__ cur,
    const float* __restrict__ pos,
    const float* __restrict__ Wkv, const float* __restrict__ Wq,
    const float* __restrict__ Wpos, const float* __restrict__ Wproj)
{
    const int id = blockIdx.x;
    if (id < NSPLIT_BLK) {
        size_t i = ((size_t)id*256 + threadIdx.x) * 4;
        const float* src; __half* dst; size_t off;
        if (i < NF_E)             { src = full; dst = g_Xf; off = i; }
        else if (i < NF_E + NC_E) { src = cur;  dst = g_Xc; off = i - NF_E; }
        else                      { src = pos;  dst = g_Xp; off = i - NF_E - NC_E; }
        float4 vv = *(const float4*)(src + off);
        *(uint32_t*)(dst + off)     = pack_half2(vv.x, vv.y);
        *(uint32_t*)(dst + off + 2) = pack_half2(vv.z, vv.w);
    } else {
        __shared__ float t[32][33];
        const int tb = id - NSPLIT_BLK;
        const int x = tb % 160, y = tb / 160;
        const float* W; __half* wd; int N, n0;
        if (x < 64)       { W = Wkv;   wd = g_Wkv; N = 2048; n0 = x*32; }
        else if (x < 96)  { W = Wq;    wd = g_Wq;  N = 1024; n0 = (x-64)*32; }
        else if (x < 128) { W = Wpos;  wd = g_Wr;  N = 1024; n0 = (x-96)*32; }
        else              { W = Wproj; wd = g_Wp;  N = 1024; n0 = (x-128)*32; }
        const int k0 = y*32;
        const int tx = threadIdx.x & 31, ty = threadIdx.x >> 5;
        #pragma unroll
        for (int i = 0; i < 32; i += 8)
            t[ty+i][tx] = W[(size_t)(k0+ty+i)*N + n0+tx];
        __syncthreads();
        #pragma unroll
        for (int i = 0; i < 32; i += 8)
            wd[(size_t)(n0+ty+i)*DIMM + k0+tx] = __float2half_rn(t[tx][ty+i]);
    }
}

// ---------------- flash attention: pipelined K/V/P, smem residual-shift P add ----------------
#define ARS 72
#define PARS 88                              // P tile row stride (conflict-free for g-rows)
#define ATILE (64*ARS)
#define PTILE (128*PARS)
#define STAGE_H (2*ATILE + PTILE)            // 20480 halves
#define AT_BYTES (2*STAGE_H*2)               // 81920 B, 2 CTAs/SM

__global__ __launch_bounds__(256, 2) void k_attn_mma()
{
    const int bh = blockIdx.y, b = bh >> 4, h = bh & 15;
    const int a0 = blockIdx.x * 128;
    extern __shared__ __half smh[];
    const uint32_t base = smem_u32(smh);

    const int tid = threadIdx.x, lane = tid & 31, w = tid >> 5;
    const int g = lane >> 2, q = lane & 3, qq2 = q*2;
    const int lr = lane & 7, gb = lane >> 3;
    const uint32_t lof = (uint32_t)((lr + (gb & 1)*8)*(ARS*2) + (gb >> 1)*16);

    const __half* Kp  = g_K + (size_t)bh*FULLL*HD;
    const __half* Vp  = g_V + (size_t)bh*FULLL*HD;
    const __half* Psh = g_P + (size_t)bh*CUR*PSTR;

    // ---- stage QU -> register A fragments (uses stage-1 buffer space) ----
    const __half* Qp = g_QU + ((size_t)bh*CUR + a0)*HD;
    uint32_t aQ[4][4];
    {
        __half* qbuf = smh + STAGE_H;
        #pragma unroll
        for (int i = 0; i < 4; i++) {
            int s = tid + (i<<8); int row = s >> 3, c = s & 7;
            *(float4*)(qbuf + row*ARS + c*8) = *(const float4*)(Qp + row*HD + c*8);
        }
        __syncthreads();
        const uint32_t bQ = base + STAGE_H*2;
        #pragma unroll
        for (int ks = 0; ks < 4; ks++) ldsm4(aQ[ks], bQ + (uint32_t)(w*16*ARS*2) + lof + ks*32);
        __syncthreads();
    }

    float oacc[8][4] = {};
    float rl0 = 0.f, rl1 = 0.f;
    const int arow0 = a0 + w*16 + g;
    const int amax = a0 + w*16 + 15;
    const int nkb = (a0 + 640) >> 6;
    const int rs = (511 - arow0) & 7;            // residual shift, same for arow0 and arow0+8
    const int prow0 = (w*16 + g)*PARS + qq2 + rs;
    const int prow1 = prow0 + 8*PARS;

    auto issue = [&](int kb, int s){
        const int j0 = kb << 6;
        const uint32_t sb = base + (uint32_t)s*(STAGE_H*2);
        #pragma unroll
        for (int i = 0; i < 2; i++) {
            int t = tid + (i<<8); int row = t >> 3, c = t & 7;
            uint32_t off = (uint32_t)(row*ARS + c*8)*2;
            size_t gi = (size_t)(j0 + row)*HD + c*8;
            cpasync16(sb + off,           Kp + gi);
            cpasync16(sb + ATILE*2 + off, Vp + gi);
        }
        // P tile: rows a0..a0+127, shifted columns j0..j0+79
        #pragma unroll
        for (int i = 0; i < 5; i++) {
            int t = tid + (i<<8);          // 0..1279
            int row = t / 10, c16 = t % 10;
            cpasync16(sb + 2*ATILE*2 + (uint32_t)(row*PARS + c16*8)*2,
                      Psh + (size_t)(a0 + row)*PSTR + j0 + c16*8);
        }
        asm volatile("cp.async.commit_group;");
    };

    issue(0, 0);
    for (int kb = 0; kb < nkb; kb++) {
        const int j0 = kb << 6;
        if (kb + 1 < nkb) {
            issue(kb + 1, (kb + 1) & 1);
            asm volatile("cp.async.wait_group 1;" ::: "memory");
        } else {
            asm volatile("cp.async.wait_group 0;" ::: "memory");
        }
        __syncthreads();
        const uint32_t bK = base + (uint32_t)(kb & 1)*(STAGE_H*2);
        const uint32_t bV = bK + ATILE*2;
        const __half* sPb = smh + (size_t)(kb & 1)*STAGE_H + 2*ATILE;

        if (j0 <= amax + 512) {
            // ---- S = QU @ K^T (pre-scaled, log2 domain) ----
            float sacc[8][4] = {};
            #pragma unroll
            for (int n16 = 0; n16 < 4; n16++) {
                #pragma unroll
                for (int ks = 0; ks < 4; ks++) {
                    uint32_t k4[4];
                    ldsm4(k4, bK + (uint32_t)(n16*16*ARS*2) + lof + ks*32);
                    mma_fp16(sacc[2*n16],   aQ[ks], k4[0], k4[2]);
                    mma_fp16(sacc[2*n16+1], aQ[ks], k4[1], k4[3]);
                }
            }

            // ---- p = exp2(S + P) with mask; accumulate raw row sums ----
            const int da = j0 - arow0;
            #pragma unroll
            for (int nf = 0; nf < 8; nf++) {
                float q0 = __half2float(sPb[prow0 + nf*8]);
                float q1 = __half2float(sPb[prow0 + nf*8 + 1]);
                float q2 = __half2float(sPb[prow1 + nf*8]);
                float q3 = __half2float(sPb[prow1 + nf*8 + 1]);
                const int e = da + nf*8 + qq2;   // j - arow0
                float p0 = (e     <= 512) ? exp2f(sacc[nf][0] + q0) : 0.f;
                float p1 = (e + 1 <= 512) ? exp2f(sacc[nf][1] + q1) : 0.f;
                float p2 = (e - 8 <= 512) ? exp2f(sacc[nf][2] + q2) : 0.f;
                float p3 = (e - 7 <= 512) ? exp2f(sacc[nf][3] + q3) : 0.f;
                sacc[nf][0] = p0; sacc[nf][1] = p1; sacc[nf][2] = p2; sacc[nf][3] = p3;
                rl0 += p0 + p1;
                rl1 += p2 + p3;
            }

            // ---- O += P~ @ V ----
            #pragma unroll
            for (int kf = 0; kf < 4; kf++) {
                uint32_t ap[4];
                ap[0] = pack_half2(sacc[2*kf][0],   sacc[2*kf][1]);
                ap[1] = pack_half2(sacc[2*kf][2],   sacc[2*kf][3]);
                ap[2] = pack_half2(sacc[2*kf+1][0], sacc[2*kf+1][1]);
                ap[3] = pack_half2(sacc[2*kf+1][2], sacc[2*kf+1][3]);
                #pragma unroll
                for (int d16 = 0; d16 < 4; d16++) {
                    uint32_t v4[4];
                    ldsm4t(v4, bV + (uint32_t)(kf*16*ARS*2) + lof + d16*32);
                    mma_fp16(oacc[2*d16],   ap, v4[0], v4[1]);
                    mma_fp16(oacc[2*d16+1], ap, v4[2], v4[3]);
                }
            }
        }
        __syncthreads();
    }

    // ---- finalize ----
    rl0 += __shfl_xor_sync(0xffffffffu, rl0, 1);
    rl0 += __shfl_xor_sync(0xffffffffu, rl0, 2);
    rl1 += __shfl_xor_sync(0xffffffffu, rl1, 1);
    rl1 += __shfl_xor_sync(0xffffffffu, rl1, 2);
    float i0 = 1.f / rl0, i1 = 1.f / rl1;
    size_t base0 = ((size_t)arow0*BSZ + b)*(NH*HD) + h*HD;
    size_t base1 = ((size_t)(arow0+8)*BSZ + b)*(NH*HD) + h*HD;
    #pragma unroll
    for (int nf = 0; nf < 8; nf++) {
        int d = nf*8 + qq2;
        *(uint32_t*)(g_AO + base0 + d) = pack_half2(oacc[nf][0]*i0, oacc[nf][1]*i0);
        *(uint32_t*)(g_AO + base1 + d) = pack_half2(oacc[nf][2]*i1, oacc[nf][3]*i1);
    }
}

// ---------------- launch ----------------
extern "C" void kernel_launch(void* const* d_in, const int* in_sizes, int n_in,
                              void* d_out, int out_size)
{
    const float* inputs     = (const float*)d_in[0];
    const float* pos_emb    = (const float*)d_in[1];
    const float* full_input = (const float*)d_in[2];
    const float* u          = (const float*)d_in[3];
    const float* v          = (const float*)d_in[4];
    // d_in[5] = mask: unused (derived analytically)
    const float* W_kv   = (const float*)d_in[6];
    const float* b_kv   = (const float*)d_in[7];
    const float* W_q    = (const float*)d_in[8];
    const float* b_q    = (const float*)d_in[9];
    const float* W_pos  = (const float*)d_in[10];
    const float* b_pos  = (const float*)d_in[11];
    const float* W_proj = (const float*)d_in[12];
    const float* b_proj = (const float*)d_in[13];
    float* out = (float*)d_out;

    cudaFuncSetAttribute(k_attn_mma, cudaFuncAttributeMaxDynamicSharedMemorySize, AT_BYTES);

    // 1. all conversions in one launch
    k_convert<<<NSPLIT_BLK + 5120, 256>>>(full_input, inputs, pos_emb,
                                          W_kv, W_q, W_pos, W_proj);
    // 2. merged KV + Q + R projection GEMMs (QU pre-scaled)
    k_gemm_projs<<<1344, 256, SM_BYTES>>>(b_kv, b_q, b_pos, u, v);
    // 3. P quantized-shift store (coalesced u32), dead tiles skipped
    k_gemm_pos<<<dim3(8, 4, 128), 256, SM_BYTES>>>();
    // 4. attention (pipelined K/V/P, residual-shift smem P add)
    k_attn_mma<<<dim3(4, 128), 256, AT_BYTES>>>();
    // 5. output projection (fused bias)
    k_gemm_proj<<<dim3(8, 32), 256, SM_BYTES>>>(b_proj, out);
}

// round 16
// speedup vs baseline: 1.1911x; 1.0176x over previous
#include <cuda_runtime.h>
#include <cuda_fp16.h>
#include <stdint.h>

#define CUR   512
#define FULLL 1024
#define BSZ   8
#define DIMM  1024
#define NH    16
#define HD    64
#define PSTR  1088    // padded row stride of shifted-P (halves)

// ---------------- scratch (device globals; allocation-free) ----------------
__device__ __half g_QU[BSZ*NH*CUR*HD], g_QV[BSZ*NH*CUR*HD];
__device__ __half g_K [BSZ*NH*FULLL*HD], g_V [BSZ*NH*FULLL*HD];
__device__ __half g_R [NH*FULLL*HD];
// quantized-shift P: P[a][m]*CSCALE stored at column c = m - ((511-a)&~7)
__device__ __half g_P [(size_t)BSZ*NH*CUR*PSTR];
// A operands
__device__ __half g_Xf[8192*1024];
__device__ __half g_Xc[4096*1024];
__device__ __half g_Xp[1024*1024];
__device__ __half g_AO[4096*1024];
// W^T operands
__device__ __half g_Wkv[2048*1024];
__device__ __half g_Wq [1024*1024];
__device__ __half g_Wr [1024*1024];
__device__ __half g_Wp [1024*1024];

#define CSCALE (0.125f * 1.44269504f)

// ---------------- helpers ----------------
__device__ __forceinline__ uint32_t smem_u32(const void* p){
    uint32_t a; asm("{ .reg .u64 t; cvta.to.shared.u64 t, %1; cvt.u32.u64 %0, t; }":"=r"(a):"l"(p)); return a;
}
__device__ __forceinline__ void ldsm4(uint32_t* r, uint32_t addr){
    asm volatile("ldmatrix.sync.aligned.m8n8.x4.shared.b16 {%0,%1,%2,%3}, [%4];"
        : "=r"(r[0]),"=r"(r[1]),"=r"(r[2]),"=r"(r[3]) : "r"(addr));
}
__device__ __forceinline__ void ldsm4t(uint32_t* r, uint32_t addr){
    asm volatile("ldmatrix.sync.aligned.m8n8.x4.trans.shared.b16 {%0,%1,%2,%3}, [%4];"
        : "=r"(r[0]),"=r"(r[1]),"=r"(r[2]),"=r"(r[3]) : "r"(addr));
}
__device__ __forceinline__ void mma_fp16(float* c, const uint32_t* a, uint32_t b0, uint32_t b1){
    asm volatile("mma.sync.aligned.m16n8k16.row.col.f32.f16.f16.f32 "
        "{%0,%1,%2,%3}, {%4,%5,%6,%7}, {%8,%9}, {%0,%1,%2,%3};"
        : "+f"(c[0]),"+f"(c[1]),"+f"(c[2]),"+f"(c[3])
        : "r"(a[0]),"r"(a[1]),"r"(a[2]),"r"(a[3]), "r"(b0),"r"(b1));
}
__device__ __forceinline__ uint32_t pack_half2(float x, float y){
    __half2 h = __floats2half2_rn(x, y);
    return *(uint32_t*)&h;
}
__device__ __forceinline__ void cpasync16(uint32_t dst, const void* src){
    asm volatile("cp.async.cg.shared.global [%0], [%1], 16;" :: "r"(dst), "l"(src));
}

// ---------------- warp-MMA fp16 GEMM core (validated round 10) ----------------
#define TSTR 72
#define TILE_ELEMS (128*TSTR)
#define SM_BYTES (2*TILE_ELEMS*2)

__device__ __forceinline__ void load_tile_async(uint32_t dsm, const __half* src, int ld){
    const int tid = threadIdx.x;
    #pragma unroll
    for (int i = 0; i < 4; i++) {
        int s = tid + (i<<8);
        int row = s >> 3, cq = s & 7;
        cpasync16(dsm + (uint32_t)(row*TSTR + cq*8)*2, src + (size_t)row*ld + cq*8);
    }
}

__device__ __forceinline__ void gemm_compute(
    const __half* pA, const __half* pB, int K, float acc[4][4][4])
{
    extern __shared__ __half smb[];
    const uint32_t base = smem_u32(smb);
    const uint32_t bA = base, bB = base + TILE_ELEMS*2;

    const int lane = threadIdx.x & 31, wid = threadIdx.x >> 5;
    const int wm = wid >> 2, wn = wid & 3;
    const int g = lane >> 3, lr = lane & 7;

    const int arow = wm*64 + lr + (g & 1)*8;
    const int kcol = (g >> 1)*8;
    uint32_t aoff[4];
    #pragma unroll
    for (int mf = 0; mf < 4; mf++) aoff[mf] = (uint32_t)(((arow + mf*16)*TSTR + kcol)*2);
    const int brow = wn*32 + lr + (g & 1)*8;
    uint32_t boff[2];
    #pragma unroll
    for (int np = 0; np < 2; np++) boff[np] = (uint32_t)(((brow + np*16)*TSTR + kcol)*2);

    const int nchunk = K >> 6;
    for (int kc = 0; kc < nchunk; kc++) {
        const int k0 = kc << 6;
        __syncthreads();
        load_tile_async(bA, pA + k0, K);
        load_tile_async(bB, pB + k0, K);
        asm volatile("cp.async.commit_group;");
        asm volatile("cp.async.wait_group 0;" ::: "memory");
        __syncthreads();
        #pragma unroll
        for (int ks = 0; ks < 4; ks++) {
            const uint32_t kb = ks*32;
            uint32_t a4[4][4], bp[2][4];
            #pragma unroll
            for (int mf = 0; mf < 4; mf++) ldsm4(a4[mf], bA + aoff[mf] + kb);
            ldsm4(bp[0], bB + boff[0] + kb);
            ldsm4(bp[1], bB + boff[1] + kb);
            #pragma unroll
            for (int mf = 0; mf < 4; mf++)
                #pragma unroll
                for (int nf = 0; nf < 4; nf++)
                    mma_fp16(acc[mf][nf], a4[mf], bp[nf>>1][nf&1], bp[nf>>1][2+(nf&1)]);
        }
    }
}

// ---------------- merged projection GEMM (KV + Q + R in one launch) ----------------
__global__ __launch_bounds__(256, 2) void k_gemm_projs(
    const float* __restrict__ b_kv, const float* __restrict__ b_q,
    const float* __restrict__ b_pos,
    const float* __restrict__ u, const float* __restrict__ v)
{
    const int id = blockIdx.x;
    const int lane = threadIdx.x & 31, wid = threadIdx.x >> 5;
    float acc[4][4][4] = {};

    if (id < 1024) {
        const int m0 = (id >> 4)*128, n0 = (id & 15)*128;
        gemm_compute(g_Xf + (size_t)m0*DIMM, g_Wkv + (size_t)n0*DIMM, DIMM, acc);
        const int r0 = m0 + (wid>>2)*64 + (lane>>2);
        const int c0 = n0 + (wid&3)*32 + (lane&3)*2;
        #pragma unroll
        for (int nf = 0; nf < 4; nf++) {
            const int n = c0 + nf*8;
            const bool isK = n < 1024;
            const int nn = n & 1023, hh = nn >> 6, d = nn & 63;
            __half* D = isK ? g_K : g_V;
            const float2 bv = *(const float2*)(b_kv + n);
            #pragma unroll
            for (int mf = 0; mf < 4; mf++) {
                int m = r0 + mf*16;
                int f = m >> 3, b = m & 7;
                size_t o = (((size_t)(b*NH + hh)*FULLL) + f)*HD + d;
                *(uint32_t*)(D + o)      = pack_half2(acc[mf][nf][0] + bv.x, acc[mf][nf][1] + bv.y);
                *(uint32_t*)(D + o + HD) = pack_half2(acc[mf][nf][2] + bv.x, acc[mf][nf][3] + bv.y);
            }
        }
    } else if (id < 1280) {
        const int t = id - 1024;
        const int m0 = (t >> 3)*128, n0 = (t & 7)*128;
        gemm_compute(g_Xc + (size_t)m0*DIMM, g_Wq + (size_t)n0*DIMM, DIMM, acc);
        const int r0 = m0 + (wid>>2)*64 + (lane>>2);
        const int c0 = n0 + (wid&3)*32 + (lane&3)*2;
        #pragma unroll
        for (int nf = 0; nf < 4; nf++) {
            const int n = c0 + nf*8;
            const int hh = n >> 6, d = n & 63;
            const float2 bv = *(const float2*)(b_q + n);
            const float2 uv = *(const float2*)(u + n);
            const float2 vv = *(const float2*)(v + n);
            #pragma unroll
            for (int mf = 0; mf < 4; mf++) {
                int m = r0 + mf*16;
                int c = m >> 3, b = m & 7;
                size_t o = (((size_t)(b*NH + hh)*CUR) + c)*HD + d;
                float x0 = acc[mf][nf][0] + bv.x, x1 = acc[mf][nf][1] + bv.y;
                *(uint32_t*)(g_QU + o) = pack_half2((x0 + uv.x)*CSCALE, (x1 + uv.y)*CSCALE);
                *(uint32_t*)(g_QV + o) = pack_half2(x0 + vv.x, x1 + vv.y);
                float y0 = acc[mf][nf][2] + bv.x, y1 = acc[mf][nf][3] + bv.y;
                *(uint32_t*)(g_QU + o + HD) = pack_half2((y0 + uv.x)*CSCALE, (y1 + uv.y)*CSCALE);
                *(uint32_t*)(g_QV + o + HD) = pack_half2(y0 + vv.x, y1 + vv.y);
            }
        }
    } else {
        const int t = id - 1280;
        const int m0 = (t >> 3)*128, n0 = (t & 7)*128;
        gemm_compute(g_Xp + (size_t)m0*DIMM, g_Wr + (size_t)n0*DIMM, DIMM, acc);
        const int r0 = m0 + (wid>>2)*64 + (lane>>2);
        const int c0 = n0 + (wid&3)*32 + (lane&3)*2;
        #pragma unroll
        for (int nf = 0; nf < 4; nf++) {
            const int n = c0 + nf*8;
            const int hh = n >> 6, d = n & 63;
            const float2 bv = *(const float2*)(b_pos + n);
            #pragma unroll
            for (int mf = 0; mf < 4; mf++) {
                int tt = r0 + mf*16;
                size_t o = ((size_t)hh*FULLL + tt)*HD + d;
                *(uint32_t*)(g_R + o)        = pack_half2(acc[mf][nf][0] + bv.x, acc[mf][nf][1] + bv.y);
                *(uint32_t*)(g_R + o + 8*HD) = pack_half2(acc[mf][nf][2] + bv.x, acc[mf][nf][3] + bv.y);
            }
        }
    }
}

// ---------------- P quantized-shift store: P[a][m] -> column m - ((511-a)&~7) ----------------
__global__ __launch_bounds__(256, 2) void k_gemm_pos()
{
    const int m_blk = blockIdx.x, a_blk = blockIdx.y;
    if (a_blk + m_blk <= 2) return;   // never read
    const int bh = blockIdx.z, hh = bh & 15;
    const int m0 = a_blk*128, n0 = m_blk*128;
    float acc[4][4][4] = {};
    gemm_compute(g_QV + ((size_t)bh*CUR + m0)*HD,
                 g_R  + ((size_t)hh*FULLL + n0)*HD, HD, acc);
    __half* Pp = g_P + (size_t)bh*CUR*PSTR;
    const int lane = threadIdx.x & 31, wid = threadIdx.x >> 5;
    const int r0 = m0 + (wid>>2)*64 + (lane>>2);
    const int c0 = n0 + (wid&3)*32 + (lane&3)*2;
    #pragma unroll
    for (int mf = 0; mf < 4; mf++) {
        const int ar = r0 + mf*16;
        const int q1 = (511 - ar) & ~7;
        const int q2 = (511 - ar - 8) & ~7;
        #pragma unroll
        for (int nf = 0; nf < 4; nf++) {
            const int m = c0 + nf*8;
            const int c1 = m - q1, c2 = m - q2;
            if ((unsigned)c1 < 1024u)
                *(uint32_t*)(Pp + (size_t)ar*PSTR + c1) =
                    pack_half2(acc[mf][nf][0]*CSCALE, acc[mf][nf][1]*CSCALE);
            if ((unsigned)c2 < 1024u)
                *(uint32_t*)(Pp + (size_t)(ar+8)*PSTR + c2) =
                    pack_half2(acc[mf][nf][2]*CSCALE, acc[mf][nf][3]*CSCALE);
        }
    }
}

// ---------------- output projection ----------------
__global__ __launch_bounds__(256, 2) void k_gemm_proj(const float* __restrict__ bias,
                                                      float* __restrict__ out)
{
    const int m0 = blockIdx.y*128, n0 = blockIdx.x*128;
    float acc[4][4][4] = {};
    gemm_compute(g_AO + (size_t)m0*DIMM, g_Wp + (size_t)n0*DIMM, DIMM, acc);
    const int lane = threadIdx.x & 31, wid = threadIdx.x >> 5;
    const int r0 = m0 + (wid>>2)*64 + (lane>>2);
    const int c0 = n0 + (wid&3)*32 + (lane&3)*2;
    #pragma unroll
    for (int nf = 0; nf < 4; nf++) {
        const float2 bv = *(const float2*)(bias + c0 + nf*8);
        #pragma unroll
        for (int mf = 0; mf < 4; mf++) {
            float* p = out + (size_t)(r0 + mf*16)*DIMM + c0 + nf*8;
            *(float2*)p            = make_float2(acc[mf][nf][0] + bv.x, acc[mf][nf][1] + bv.y);
            *(float2*)(p + 8*DIMM) = make_float2(acc[mf][nf][2] + bv.x, acc[mf][nf][3] + bv.y);
        }
    }
}

// ---------------- single merged conversion kernel ----------------
#define NF_E (8192*1024)
#define NC_E (4096*1024)
#define NP_E (1024*1024)
#define NSPLIT_BLK ((NF_E + NC_E + NP_E)/1024)

__global__ __launch_bounds__(256) void k_convert(
    const float* __restrict__ full, const float* __restrict__ cur,
    const float* __restrict__ pos,
    const float* __restrict__ Wkv, const float* __restrict__ Wq,
    const float* __restrict__ Wpos, const float* __restrict__ Wproj)
{
    const int id = blockIdx.x;
    if (id < NSPLIT_BLK) {
        size_t i = ((size_t)id*256 + threadIdx.x) * 4;
        const float* src; __half* dst; size_t off;
        if (i < NF_E)             { src = full; dst = g_Xf; off = i; }
        else if (i < NF_E + NC_E) { src = cur;  dst = g_Xc; off = i - NF_E; }
        else                      { src = pos;  dst = g_Xp; off = i - NF_E - NC_E; }
        float4 vv = *(const float4*)(src + off);
        *(uint32_t*)(dst + off)     = pack_half2(vv.x, vv.y);
        *(uint32_t*)(dst + off + 2) = pack_half2(vv.z, vv.w);
    } else {
        __shared__ float t[32][33];
        const int tb = id - NSPLIT_BLK;
        const int x = tb % 160, y = tb / 160;
        const float* W; __half* wd; int N, n0;
        if (x < 64)       { W = Wkv;   wd = g_Wkv; N = 2048; n0 = x*32; }
        else if (x < 96)  { W = Wq;    wd = g_Wq;  N = 1024; n0 = (x-64)*32; }
        else if (x < 128) { W = Wpos;  wd = g_Wr;  N = 1024; n0 = (x-96)*32; }
        else              { W = Wproj; wd = g_Wp;  N = 1024; n0 = (x-128)*32; }
        const int k0 = y*32;
        const int tx = threadIdx.x & 31, ty = threadIdx.x >> 5;
        #pragma unroll
        for (int i = 0; i < 32; i += 8)
            t[ty+i][tx] = W[(size_t)(k0+ty+i)*N + n0+tx];
        __syncthreads();
        #pragma unroll
        for (int i = 0; i < 32; i += 8)
            wd[(size_t)(n0+ty+i)*DIMM + k0+tx] = __float2half_rn(t[tx][ty+i]);
    }
}

// ---------------- flash attention: pipelined K/V/P, P preloaded into accumulators ----------------
#define ARS 72
#define PARS 88
#define ATILE (64*ARS)
#define PTILE (128*PARS)
#define STAGE_H (2*ATILE + PTILE)
#define AT_BYTES (2*STAGE_H*2)   // 81920 B, 2 CTAs/SM

__global__ __launch_bounds__(256, 2) void k_attn_mma()
{
    const int bh = blockIdx.y, b = bh >> 4, h = bh & 15;
    const int a0 = blockIdx.x * 128;
    extern __shared__ __half smh[];
    const uint32_t base = smem_u32(smh);

    const int tid = threadIdx.x, lane = tid & 31, w = tid >> 5;
    const int g = lane >> 2, q = lane & 3, qq2 = q*2;
    const int lr = lane & 7, gb = lane >> 3;
    const uint32_t lof = (uint32_t)((lr + (gb & 1)*8)*(ARS*2) + (gb >> 1)*16);

    const __half* Kp  = g_K + (size_t)bh*FULLL*HD;
    const __half* Vp  = g_V + (size_t)bh*FULLL*HD;
    const __half* Psh = g_P + (size_t)bh*CUR*PSTR;

    // ---- stage QU -> register A fragments (uses stage-1 buffer space) ----
    const __half* Qp = g_QU + ((size_t)bh*CUR + a0)*HD;
    uint32_t aQ[4][4];
    {
        __half* qbuf = smh + STAGE_H;
        #pragma unroll
        for (int i = 0; i < 4; i++) {
            int s = tid + (i<<8); int row = s >> 3, c = s & 7;
            *(float4*)(qbuf + row*ARS + c*8) = *(const float4*)(Qp + row*HD + c*8);
        }
        __syncthreads();
        const uint32_t bQ = base + STAGE_H*2;
        #pragma unroll
        for (int ks = 0; ks < 4; ks++) ldsm4(aQ[ks], bQ + (uint32_t)(w*16*ARS*2) + lof + ks*32);
        __syncthreads();
    }

    float oacc[8][4] = {};
    float rl0 = 0.f, rl1 = 0.f;
    const int arow0 = a0 + w*16 + g;
    const int amax = a0 + w*16 + 15;
    const int nkb = (a0 + 640) >> 6;
    const int rs = (511 - arow0) & 7;
    const int prow0 = (w*16 + g)*PARS + qq2 + rs;
    const int prow1 = prow0 + 8*PARS;

    auto issue = [&](int kb, int s){
        const int j0 = kb << 6;
        const uint32_t sb = base + (uint32_t)s*(STAGE_H*2);
        #pragma unroll
        for (int i = 0; i < 2; i++) {
            int t = tid + (i<<8); int row = t >> 3, c = t & 7;
            uint32_t off = (uint32_t)(row*ARS + c*8)*2;
            size_t gi = (size_t)(j0 + row)*HD + c*8;
            cpasync16(sb + off,           Kp + gi);
            cpasync16(sb + ATILE*2 + off, Vp + gi);
        }
        #pragma unroll
        for (int i = 0; i < 5; i++) {
            int t = tid + (i<<8);
            int row = t / 10, c16 = t % 10;
            cpasync16(sb + 2*ATILE*2 + (uint32_t)(row*PARS + c16*8)*2,
                      Psh + (size_t)(a0 + row)*PSTR + j0 + c16*8);
        }
        asm volatile("cp.async.commit_group;");
    };

    issue(0, 0);
    for (int kb = 0; kb < nkb; kb++) {
        const int j0 = kb << 6;
        if (kb + 1 < nkb) {
            issue(kb + 1, (kb + 1) & 1);
            asm volatile("cp.async.wait_group 1;" ::: "memory");
        } else {
            asm volatile("cp.async.wait_group 0;" ::: "memory");
        }
        __syncthreads();
        const uint32_t bK = base + (uint32_t)(kb & 1)*(STAGE_H*2);
        const uint32_t bV = bK + ATILE*2;
        const __half* sPb = smh + (size_t)(kb & 1)*STAGE_H + 2*ATILE;

        if (j0 <= amax + 512) {
            // ---- init S accumulators with P (LDS issues before MMA block,
            //      latency hidden under HMMA; add fused into accumulation) ----
            float sacc[8][4];
            #pragma unroll
            for (int nf = 0; nf < 8; nf++) {
                sacc[nf][0] = __half2float(sPb[prow0 + nf*8]);
                sacc[nf][1] = __half2float(sPb[prow0 + nf*8 + 1]);
                sacc[nf][2] = __half2float(sPb[prow1 + nf*8]);
                sacc[nf][3] = __half2float(sPb[prow1 + nf*8 + 1]);
            }

            // ---- S += QU @ K^T (pre-scaled, log2 domain) ----
            #pragma unroll
            for (int n16 = 0; n16 < 4; n16++) {
                #pragma unroll
                for (int ks = 0; ks < 4; ks++) {
                    uint32_t k4[4];
                    ldsm4(k4, bK + (uint32_t)(n16*16*ARS*2) + lof + ks*32);
                    mma_fp16(sacc[2*n16],   aQ[ks], k4[0], k4[2]);
                    mma_fp16(sacc[2*n16+1], aQ[ks], k4[1], k4[3]);
                }
            }

            // ---- p = exp2(S) with mask; accumulate raw row sums ----
            const int da = j0 - arow0;
            #pragma unroll
            for (int nf = 0; nf < 8; nf++) {
                const int e = da + nf*8 + qq2;   // j - arow0
                float p0 = (e     <= 512) ? exp2f(sacc[nf][0]) : 0.f;
                float p1 = (e + 1 <= 512) ? exp2f(sacc[nf][1]) : 0.f;
                float p2 = (e - 8 <= 512) ? exp2f(sacc[nf][2]) : 0.f;
                float p3 = (e - 7 <= 512) ? exp2f(sacc[nf][3]) : 0.f;
                sacc[nf][0] = p0; sacc[nf][1] = p1; sacc[nf][2] = p2; sacc[nf][3] = p3;
                rl0 += p0 + p1;
                rl1 += p2 + p3;
            }

            // ---- O += P~ @ V ----
            #pragma unroll
            for (int kf = 0; kf < 4; kf++) {
                uint32_t ap[4];
                ap[0] = pack_half2(sacc[2*kf][0],   sacc[2*kf][1]);
                ap[1] = pack_half2(sacc[2*kf][2],   sacc[2*kf][3]);
                ap[2] = pack_half2(sacc[2*kf+1][0], sacc[2*kf+1][1]);
                ap[3] = pack_half2(sacc[2*kf+1][2], sacc[2*kf+1][3]);
                #pragma unroll
                for (int d16 = 0; d16 < 4; d16++) {
                    uint32_t v4[4];
                    ldsm4t(v4, bV + (uint32_t)(kf*16*ARS*2) + lof + d16*32);
                    mma_fp16(oacc[2*d16],   ap, v4[0], v4[1]);
                    mma_fp16(oacc[2*d16+1], ap, v4[2], v4[3]);
                }
            }
        }
        __syncthreads();
    }

    // ---- finalize ----
    rl0 += __shfl_xor_sync(0xffffffffu, rl0, 1);
    rl0 += __shfl_xor_sync(0xffffffffu, rl0, 2);
    rl1 += __shfl_xor_sync(0xffffffffu, rl1, 1);
    rl1 += __shfl_xor_sync(0xffffffffu, rl1, 2);
    float i0 = 1.f / rl0, i1 = 1.f / rl1;
    size_t base0 = ((size_t)arow0*BSZ + b)*(NH*HD) + h*HD;
    size_t base1 = ((size_t)(arow0+8)*BSZ + b)*(NH*HD) + h*HD;
    #pragma unroll
    for (int nf = 0; nf < 8; nf++) {
        int d = nf*8 + qq2;
        *(uint32_t*)(g_AO + base0 + d) = pack_half2(oacc[nf][0]*i0, oacc[nf][1]*i0);
        *(uint32_t*)(g_AO + base1 + d) = pack_half2(oacc[nf][2]*i1, oacc[nf][3]*i1);
    }
}

// ---------------- launch ----------------
extern "C" void kernel_launch(void* const* d_in, const int* in_sizes, int n_in,
                              void* d_out, int out_size)
{
    const float* inputs     = (const float*)d_in[0];
    const float* pos_emb    = (const float*)d_in[1];
    const float* full_input = (const float*)d_in[2];
    const float* u          = (const float*)d_in[3];
    const float* v          = (const float*)d_in[4];
    // d_in[5] = mask: unused (derived analytically)
    const float* W_kv   = (const float*)d_in[6];
    const float* b_kv   = (const float*)d_in[7];
    const float* W_q    = (const float*)d_in[8];
    const float* b_q    = (const float*)d_in[9];
    const float* W_pos  = (const float*)d_in[10];
    const float* b_pos  = (const float*)d_in[11];
    const float* W_proj = (const float*)d_in[12];
    const float* b_proj = (const float*)d_in[13];
    float* out = (float*)d_out;

    cudaFuncSetAttribute(k_attn_mma, cudaFuncAttributeMaxDynamicSharedMemorySize, AT_BYTES);

    // 1. all conversions in one launch
    k_convert<<<NSPLIT_BLK + 5120, 256>>>(full_input, inputs, pos_emb,
                                          W_kv, W_q, W_pos, W_proj);
    // 2. merged KV + Q + R projection GEMMs (QU pre-scaled)
    k_gemm_projs<<<1344, 256, SM_BYTES>>>(b_kv, b_q, b_pos, u, v);
    // 3. P quantized-shift store (coalesced u32), dead tiles skipped
    k_gemm_pos<<<dim3(8, 4, 128), 256, SM_BYTES>>>();
    // 4. attention (pipelined K/V/P, P preloaded into accumulators)
    k_attn_mma<<<dim3(4, 128), 256, AT_BYTES>>>();
    // 5. output projection (fused bias)
    k_gemm_proj<<<dim3(8, 32), 256, SM_BYTES>>>(b_proj, out);
}

// round 17
// speedup vs baseline: 1.2613x; 1.0590x over previous
#include <cuda_runtime.h>
#include <cuda_fp16.h>
#include <stdint.h>

#define CUR   512
#define FULLL 1024
#define BSZ   8
#define DIMM  1024
#define NH    16
#define HD    64
#define PSTR  1088    // padded row stride of shifted-P (halves)

// ---------------- scratch (device globals; allocation-free) ----------------
__device__ __half g_QU[BSZ*NH*CUR*HD], g_QV[BSZ*NH*CUR*HD];
__device__ __half g_K [BSZ*NH*FULLL*HD], g_V [BSZ*NH*FULLL*HD];
__device__ __half g_R [NH*FULLL*HD];
// quantized-shift P: P[a][m]*CSCALE stored at column c = m - ((511-a)&~7)
__device__ __half g_P [(size_t)BSZ*NH*CUR*PSTR];
// A operands
__device__ __half g_Xf[8192*1024];
__device__ __half g_Xc[4096*1024];
__device__ __half g_Xp[1024*1024];
__device__ __half g_AO[4096*1024];
// W^T operands
__device__ __half g_Wkv[2048*1024];
__device__ __half g_Wq [1024*1024];
__device__ __half g_Wr [1024*1024];
__device__ __half g_Wp [1024*1024];

#define CSCALE (0.125f * 1.44269504f)

// ---------------- helpers ----------------
__device__ __forceinline__ uint32_t smem_u32(const void* p){
    uint32_t a; asm("{ .reg .u64 t; cvta.to.shared.u64 t, %1; cvt.u32.u64 %0, t; }":"=r"(a):"l"(p)); return a;
}
__device__ __forceinline__ void ldsm4(uint32_t* r, uint32_t addr){
    asm volatile("ldmatrix.sync.aligned.m8n8.x4.shared.b16 {%0,%1,%2,%3}, [%4];"
        : "=r"(r[0]),"=r"(r[1]),"=r"(r[2]),"=r"(r[3]) : "r"(addr));
}
__device__ __forceinline__ void ldsm4t(uint32_t* r, uint32_t addr){
    asm volatile("ldmatrix.sync.aligned.m8n8.x4.trans.shared.b16 {%0,%1,%2,%3}, [%4];"
        : "=r"(r[0]),"=r"(r[1]),"=r"(r[2]),"=r"(r[3]) : "r"(addr));
}
__device__ __forceinline__ void mma_fp16(float* c, const uint32_t* a, uint32_t b0, uint32_t b1){
    asm volatile("mma.sync.aligned.m16n8k16.row.col.f32.f16.f16.f32 "
        "{%0,%1,%2,%3}, {%4,%5,%6,%7}, {%8,%9}, {%0,%1,%2,%3};"
        : "+f"(c[0]),"+f"(c[1]),"+f"(c[2]),"+f"(c[3])
        : "r"(a[0]),"r"(a[1]),"r"(a[2]),"r"(a[3]), "r"(b0),"r"(b1));
}
__device__ __forceinline__ uint32_t pack_half2(float x, float y){
    __half2 h = __floats2half2_rn(x, y);
    return *(uint32_t*)&h;
}
__device__ __forceinline__ void cpasync16(uint32_t dst, const void* src){
    asm volatile("cp.async.cg.shared.global [%0], [%1], 16;" :: "r"(dst), "l"(src));
}

// ---------------- warp-MMA fp16 GEMM core: 2-stage pipeline @ 2 CTAs/SM ----------------
#define TSTR 72
#define TILE_ELEMS (128*TSTR)
#define STAGE_E (2*TILE_ELEMS)          // A+B halves per stage
#define SM_BYTES (2*STAGE_E*2)          // 73728 B per CTA -> 2 CTAs/SM

__device__ __forceinline__ void load_tile_async(uint32_t dsm, const __half* src, int ld){
    const int tid = threadIdx.x;
    #pragma unroll
    for (int i = 0; i < 4; i++) {
        int s = tid + (i<<8);
        int row = s >> 3, cq = s & 7;
        cpasync16(dsm + (uint32_t)(row*TSTR + cq*8)*2, src + (size_t)row*ld + cq*8);
    }
}

__device__ __forceinline__ void gemm_compute(
    const __half* pA, const __half* pB, int K, float acc[4][4][4])
{
    extern __shared__ __half smb[];
    const uint32_t base = smem_u32(smb);

    const int lane = threadIdx.x & 31, wid = threadIdx.x >> 5;
    const int wm = wid >> 2, wn = wid & 3;
    const int g = lane >> 3, lr = lane & 7;

    const int arow = wm*64 + lr + (g & 1)*8;
    const int kcol = (g >> 1)*8;
    uint32_t aoff[4];
    #pragma unroll
    for (int mf = 0; mf < 4; mf++) aoff[mf] = (uint32_t)(((arow + mf*16)*TSTR + kcol)*2);
    const int brow = wn*32 + lr + (g & 1)*8;
    uint32_t boff[2];
    #pragma unroll
    for (int np = 0; np < 2; np++) boff[np] = (uint32_t)(((brow + np*16)*TSTR + kcol)*2);

    const int nchunk = K >> 6;

    auto issue = [&](int kc, int s){
        const uint32_t sb = base + (uint32_t)s*(STAGE_E*2);
        const int k0 = kc << 6;
        load_tile_async(sb,                pA + k0, K);
        load_tile_async(sb + TILE_ELEMS*2, pB + k0, K);
        asm volatile("cp.async.commit_group;");
    };

    issue(0, 0);
    for (int kc = 0; kc < nchunk; kc++) {
        asm volatile("cp.async.wait_group 0;" ::: "memory");
        __syncthreads();   // stage kc visible to all; prior readers of the other stage done
        if (kc + 1 < nchunk) issue(kc + 1, (kc + 1) & 1);   // overlaps with compute below
        const uint32_t bA = base + (uint32_t)(kc & 1)*(STAGE_E*2);
        const uint32_t bB = bA + TILE_ELEMS*2;
        #pragma unroll
        for (int ks = 0; ks < 4; ks++) {
            const uint32_t kb = ks*32;
            uint32_t a4[4][4], bp[2][4];
            #pragma unroll
            for (int mf = 0; mf < 4; mf++) ldsm4(a4[mf], bA + aoff[mf] + kb);
            ldsm4(bp[0], bB + boff[0] + kb);
            ldsm4(bp[1], bB + boff[1] + kb);
            #pragma unroll
            for (int mf = 0; mf < 4; mf++)
                #pragma unroll
                for (int nf = 0; nf < 4; nf++)
                    mma_fp16(acc[mf][nf], a4[mf], bp[nf>>1][nf&1], bp[nf>>1][2+(nf&1)]);
        }
    }
}

// ---------------- merged projection GEMM (KV + Q + R in one launch) ----------------
__global__ __launch_bounds__(256, 2) void k_gemm_projs(
    const float* __restrict__ b_kv, const float* __restrict__ b_q,
    const float* __restrict__ b_pos,
    const float* __restrict__ u, const float* __restrict__ v)
{
    const int id = blockIdx.x;
    const int lane = threadIdx.x & 31, wid = threadIdx.x >> 5;
    float acc[4][4][4] = {};

    if (id < 1024) {
        const int m0 = (id >> 4)*128, n0 = (id & 15)*128;
        gemm_compute(g_Xf + (size_t)m0*DIMM, g_Wkv + (size_t)n0*DIMM, DIMM, acc);
        const int r0 = m0 + (wid>>2)*64 + (lane>>2);
        const int c0 = n0 + (wid&3)*32 + (lane&3)*2;
        #pragma unroll
        for (int nf = 0; nf < 4; nf++) {
            const int n = c0 + nf*8;
            const bool isK = n < 1024;
            const int nn = n & 1023, hh = nn >> 6, d = nn & 63;
            __half* D = isK ? g_K : g_V;
            const float2 bv = *(const float2*)(b_kv + n);
            #pragma unroll
            for (int mf = 0; mf < 4; mf++) {
                int m = r0 + mf*16;
                int f = m >> 3, b = m & 7;
                size_t o = (((size_t)(b*NH + hh)*FULLL) + f)*HD + d;
                *(uint32_t*)(D + o)      = pack_half2(acc[mf][nf][0] + bv.x, acc[mf][nf][1] + bv.y);
                *(uint32_t*)(D + o + HD) = pack_half2(acc[mf][nf][2] + bv.x, acc[mf][nf][3] + bv.y);
            }
        }
    } else if (id < 1280) {
        const int t = id - 1024;
        const int m0 = (t >> 3)*128, n0 = (t & 7)*128;
        gemm_compute(g_Xc + (size_t)m0*DIMM, g_Wq + (size_t)n0*DIMM, DIMM, acc);
        const int r0 = m0 + (wid>>2)*64 + (lane>>2);
        const int c0 = n0 + (wid&3)*32 + (lane&3)*2;
        #pragma unroll
        for (int nf = 0; nf < 4; nf++) {
            const int n = c0 + nf*8;
            const int hh = n >> 6, d = n & 63;
            const float2 bv = *(const float2*)(b_q + n);
            const float2 uv = *(const float2*)(u + n);
            const float2 vv = *(const float2*)(v + n);
            #pragma unroll
            for (int mf = 0; mf < 4; mf++) {
                int m = r0 + mf*16;
                int c = m >> 3, b = m & 7;
                size_t o = (((size_t)(b*NH + hh)*CUR) + c)*HD + d;
                float x0 = acc[mf][nf][0] + bv.x, x1 = acc[mf][nf][1] + bv.y;
                *(uint32_t*)(g_QU + o) = pack_half2((x0 + uv.x)*CSCALE, (x1 + uv.y)*CSCALE);
                *(uint32_t*)(g_QV + o) = pack_half2(x0 + vv.x, x1 + vv.y);
                float y0 = acc[mf][nf][2] + bv.x, y1 = acc[mf][nf][3] + bv.y;
                *(uint32_t*)(g_QU + o + HD) = pack_half2((y0 + uv.x)*CSCALE, (y1 + uv.y)*CSCALE);
                *(uint32_t*)(g_QV + o + HD) = pack_half2(y0 + vv.x, y1 + vv.y);
            }
        }
    } else {
        const int t = id - 1280;
        const int m0 = (t >> 3)*128, n0 = (t & 7)*128;
        gemm_compute(g_Xp + (size_t)m0*DIMM, g_Wr + (size_t)n0*DIMM, DIMM, acc);
        const int r0 = m0 + (wid>>2)*64 + (lane>>2);
        const int c0 = n0 + (wid&3)*32 + (lane&3)*2;
        #pragma unroll
        for (int nf = 0; nf < 4; nf++) {
            const int n = c0 + nf*8;
            const int hh = n >> 6, d = n & 63;
            const float2 bv = *(const float2*)(b_pos + n);
            #pragma unroll
            for (int mf = 0; mf < 4; mf++) {
                int tt = r0 + mf*16;
                size_t o = ((size_t)hh*FULLL + tt)*HD + d;
                *(uint32_t*)(g_R + o)        = pack_half2(acc[mf][nf][0] + bv.x, acc[mf][nf][1] + bv.y);
                *(uint32_t*)(g_R + o + 8*HD) = pack_half2(acc[mf][nf][2] + bv.x, acc[mf][nf][3] + bv.y);
            }
        }
    }
}

// ---------------- P quantized-shift store: P[a][m] -> column m - ((511-a)&~7) ----------------
__global__ __launch_bounds__(256, 2) void k_gemm_pos()
{
    const int m_blk = blockIdx.x, a_blk = blockIdx.y;
    if (a_blk + m_blk <= 2) return;   // never read
    const int bh = blockIdx.z, hh = bh & 15;
    const int m0 = a_blk*128, n0 = m_blk*128;
    float acc[4][4][4] = {};
    gemm_compute(g_QV + ((size_t)bh*CUR + m0)*HD,
                 g_R  + ((size_t)hh*FULLL + n0)*HD, HD, acc);
    __half* Pp = g_P + (size_t)bh*CUR*PSTR;
    const int lane = threadIdx.x & 31, wid = threadIdx.x >> 5;
    const int r0 = m0 + (wid>>2)*64 + (lane>>2);
    const int c0 = n0 + (wid&3)*32 + (lane&3)*2;
    #pragma unroll
    for (int mf = 0; mf < 4; mf++) {
        const int ar = r0 + mf*16;
        const int q1 = (511 - ar) & ~7;
        const int q2 = (511 - ar - 8) & ~7;
        #pragma unroll
        for (int nf = 0; nf < 4; nf++) {
            const int m = c0 + nf*8;
            const int c1 = m - q1, c2 = m - q2;
            if ((unsigned)c1 < 1024u)
                *(uint32_t*)(Pp + (size_t)ar*PSTR + c1) =
                    pack_half2(acc[mf][nf][0]*CSCALE, acc[mf][nf][1]*CSCALE);
            if ((unsigned)c2 < 1024u)
                *(uint32_t*)(Pp + (size_t)(ar+8)*PSTR + c2) =
                    pack_half2(acc[mf][nf][2]*CSCALE, acc[mf][nf][3]*CSCALE);
        }
    }
}

// ---------------- output projection ----------------
__global__ __launch_bounds__(256, 2) void k_gemm_proj(const float* __restrict__ bias,
                                                      float* __restrict__ out)
{
    const int m0 = blockIdx.y*128, n0 = blockIdx.x*128;
    float acc[4][4][4] = {};
    gemm_compute(g_AO + (size_t)m0*DIMM, g_Wp + (size_t)n0*DIMM, DIMM, acc);
    const int lane = threadIdx.x & 31, wid = threadIdx.x >> 5;
    const int r0 = m0 + (wid>>2)*64 + (lane>>2);
    const int c0 = n0 + (wid&3)*32 + (lane&3)*2;
    #pragma unroll
    for (int nf = 0; nf < 4; nf++) {
        const float2 bv = *(const float2*)(bias + c0 + nf*8);
        #pragma unroll
        for (int mf = 0; mf < 4; mf++) {
            float* p = out + (size_t)(r0 + mf*16)*DIMM + c0 + nf*8;
            *(float2*)p            = make_float2(acc[mf][nf][0] + bv.x, acc[mf][nf][1] + bv.y);
            *(float2*)(p + 8*DIMM) = make_float2(acc[mf][nf][2] + bv.x, acc[mf][nf][3] + bv.y);
        }
    }
}

// ---------------- single merged conversion kernel ----------------
#define NF_E (8192*1024)
#define NC_E (4096*1024)
#define NP_E (1024*1024)
#define NSPLIT_BLK ((NF_E + NC_E + NP_E)/1024)

__global__ __launch_bounds__(256) void k_convert(
    const float* __restrict__ full, const float* __restrict__ cur,
    const float* __restrict__ pos,
    const float* __restrict__ Wkv, const float* __restrict__ Wq,
    const float* __restrict__ Wpos, const float* __restrict__ Wproj)
{
    const int id = blockIdx.x;
    if (id < NSPLIT_BLK) {
        size_t i = ((size_t)id*256 + threadIdx.x) * 4;
        const float* src; __half* dst; size_t off;
        if (i < NF_E)             { src = full; dst = g_Xf; off = i; }
        else if (i < NF_E + NC_E) { src = cur;  dst = g_Xc; off = i - NF_E; }
        else                      { src = pos;  dst = g_Xp; off = i - NF_E - NC_E; }
        float4 vv = *(const float4*)(src + off);
        *(uint32_t*)(dst + off)     = pack_half2(vv.x, vv.y);
        *(uint32_t*)(dst + off + 2) = pack_half2(vv.z, vv.w);
    } else {
        __shared__ float t[32][33];
        const int tb = id - NSPLIT_BLK;
        const int x = tb % 160, y = tb / 160;
        const float* W; __half* wd; int N, n0;
        if (x < 64)       { W = Wkv;   wd = g_Wkv; N = 2048; n0 = x*32; }
        else if (x < 96)  { W = Wq;    wd = g_Wq;  N = 1024; n0 = (x-64)*32; }
        else if (x < 128) { W = Wpos;  wd = g_Wr;  N = 1024; n0 = (x-96)*32; }
        else              { W = Wproj; wd = g_Wp;  N = 1024; n0 = (x-128)*32; }
        const int k0 = y*32;
        const int tx = threadIdx.x & 31, ty = threadIdx.x >> 5;
        #pragma unroll
        for (int i = 0; i < 32; i += 8)
            t[ty+i][tx] = W[(size_t)(k0+ty+i)*N + n0+tx];
        __syncthreads();
        #pragma unroll
        for (int i = 0; i < 32; i += 8)
            wd[(size_t)(n0+ty+i)*DIMM + k0+tx] = __float2half_rn(t[tx][ty+i]);
    }
}

// ---------------- flash attention: single-sync pipelined K/V/P, P in accumulators ----------------
#define ARS 72
#define PARS 88
#define ATILE (64*ARS)
#define PTILE (128*PARS)
#define STAGE_H (2*ATILE + PTILE)
#define AT_BYTES (2*STAGE_H*2)   // 81920 B, 2 CTAs/SM

__global__ __launch_bounds__(256, 2) void k_attn_mma()
{
    const int bh = blockIdx.y, b = bh >> 4, h = bh & 15;
    const int a0 = blockIdx.x * 128;
    extern __shared__ __half smh[];
    const uint32_t base = smem_u32(smh);

    const int tid = threadIdx.x, lane = tid & 31, w = tid >> 5;
    const int g = lane >> 2, q = lane & 3, qq2 = q*2;
    const int lr = lane & 7, gb = lane >> 3;
    const uint32_t lof = (uint32_t)((lr + (gb & 1)*8)*(ARS*2) + (gb >> 1)*16);

    const __half* Kp  = g_K + (size_t)bh*FULLL*HD;
    const __half* Vp  = g_V + (size_t)bh*FULLL*HD;
    const __half* Psh = g_P + (size_t)bh*CUR*PSTR;

    // ---- stage QU -> register A fragments (uses stage-1 buffer space) ----
    const __half* Qp = g_QU + ((size_t)bh*CUR + a0)*HD;
    uint32_t aQ[4][4];
    {
        __half* qbuf = smh + STAGE_H;
        #pragma unroll
        for (int i = 0; i < 4; i++) {
            int s = tid + (i<<8); int row = s >> 3, c = s & 7;
            *(float4*)(qbuf + row*ARS + c*8) = *(const float4*)(Qp + row*HD + c*8);
        }
        __syncthreads();
        const uint32_t bQ = base + STAGE_H*2;
        #pragma unroll
        for (int ks = 0; ks < 4; ks++) ldsm4(aQ[ks], bQ + (uint32_t)(w*16*ARS*2) + lof + ks*32);
        __syncthreads();   // Q reads done before pipeline reuses stage-1 space
    }

    float oacc[8][4] = {};
    float rl0 = 0.f, rl1 = 0.f;
    const int arow0 = a0 + w*16 + g;
    const int amax = a0 + w*16 + 15;
    const int nkb = (a0 + 640) >> 6;
    const int rs = (511 - arow0) & 7;
    const int prow0 = (w*16 + g)*PARS + qq2 + rs;
    const int prow1 = prow0 + 8*PARS;

    auto issue = [&](int kb, int s){
        const int j0 = kb << 6;
        const uint32_t sb = base + (uint32_t)s*(STAGE_H*2);
        #pragma unroll
        for (int i = 0; i < 2; i++) {
            int t = tid + (i<<8); int row = t >> 3, c = t & 7;
            uint32_t off = (uint32_t)(row*ARS + c*8)*2;
            size_t gi = (size_t)(j0 + row)*HD + c*8;
            cpasync16(sb + off,           Kp + gi);
            cpasync16(sb + ATILE*2 + off, Vp + gi);
        }
        #pragma unroll
        for (int i = 0; i < 5; i++) {
            int t = tid + (i<<8);
            int row = t / 10, c16 = t % 10;
            cpasync16(sb + 2*ATILE*2 + (uint32_t)(row*PARS + c16*8)*2,
                      Psh + (size_t)(a0 + row)*PSTR + j0 + c16*8);
        }
        asm volatile("cp.async.commit_group;");
    };

    issue(0, 0);
    for (int kb = 0; kb < nkb; kb++) {
        const int j0 = kb << 6;
        asm volatile("cp.async.wait_group 0;" ::: "memory");
        __syncthreads();   // single barrier: stage kb visible; other stage free for reuse
        if (kb + 1 < nkb) issue(kb + 1, (kb + 1) & 1);   // overlaps with compute below
        const uint32_t bK = base + (uint32_t)(kb & 1)*(STAGE_H*2);
        const uint32_t bV = bK + ATILE*2;
        const __half* sPb = smh + (size_t)(kb & 1)*STAGE_H + 2*ATILE;

        if (j0 <= amax + 512) {
            // ---- init S accumulators with P (LDS hidden under HMMA) ----
            float sacc[8][4];
            #pragma unroll
            for (int nf = 0; nf < 8; nf++) {
                sacc[nf][0] = __half2float(sPb[prow0 + nf*8]);
                sacc[nf][1] = __half2float(sPb[prow0 + nf*8 + 1]);
                sacc[nf][2] = __half2float(sPb[prow1 + nf*8]);
                sacc[nf][3] = __half2float(sPb[prow1 + nf*8 + 1]);
            }

            // ---- S += QU @ K^T (pre-scaled, log2 domain) ----
            #pragma unroll
            for (int n16 = 0; n16 < 4; n16++) {
                #pragma unroll
                for (int ks = 0; ks < 4; ks++) {
                    uint32_t k4[4];
                    ldsm4(k4, bK + (uint32_t)(n16*16*ARS*2) + lof + ks*32);
                    mma_fp16(sacc[2*n16],   aQ[ks], k4[0], k4[2]);
                    mma_fp16(sacc[2*n16+1], aQ[ks], k4[1], k4[3]);
                }
            }

            // ---- p = exp2(S) with mask; accumulate raw row sums ----
            const int da = j0 - arow0;
            #pragma unroll
            for (int nf = 0; nf < 8; nf++) {
                const int e = da + nf*8 + qq2;
                float p0 = (e     <= 512) ? exp2f(sacc[nf][0]) : 0.f;
                float p1 = (e + 1 <= 512) ? exp2f(sacc[nf][1]) : 0.f;
                float p2 = (e - 8 <= 512) ? exp2f(sacc[nf][2]) : 0.f;
                float p3 = (e - 7 <= 512) ? exp2f(sacc[nf][3]) : 0.f;
                sacc[nf][0] = p0; sacc[nf][1] = p1; sacc[nf][2] = p2; sacc[nf][3] = p3;
                rl0 += p0 + p1;
                rl1 += p2 + p3;
            }

            // ---- O += P~ @ V ----
            #pragma unroll
            for (int kf = 0; kf < 4; kf++) {
                uint32_t ap[4];
                ap[0] = pack_half2(sacc[2*kf][0],   sacc[2*kf][1]);
                ap[1] = pack_half2(sacc[2*kf][2],   sacc[2*kf][3]);
                ap[2] = pack_half2(sacc[2*kf+1][0], sacc[2*kf+1][1]);
                ap[3] = pack_half2(sacc[2*kf+1][2], sacc[2*kf+1][3]);
                #pragma unroll
                for (int d16 = 0; d16 < 4; d16++) {
                    uint32_t v4[4];
                    ldsm4t(v4, bV + (uint32_t)(kf*16*ARS*2) + lof + d16*32);
                    mma_fp16(oacc[2*d16],   ap, v4[0], v4[1]);
                    mma_fp16(oacc[2*d16+1], ap, v4[2], v4[3]);
                }
            }
        }
    }

    // ---- finalize ----
    rl0 += __shfl_xor_sync(0xffffffffu, rl0, 1);
    rl0 += __shfl_xor_sync(0xffffffffu, rl0, 2);
    rl1 += __shfl_xor_sync(0xffffffffu, rl1, 1);
    rl1 += __shfl_xor_sync(0xffffffffu, rl1, 2);
    float i0 = 1.f / rl0, i1 = 1.f / rl1;
    size_t base0 = ((size_t)arow0*BSZ + b)*(NH*HD) + h*HD;
    size_t base1 = ((size_t)(arow0+8)*BSZ + b)*(NH*HD) + h*HD;
    #pragma unroll
    for (int nf = 0; nf < 8; nf++) {
        int d = nf*8 + qq2;
        *(uint32_t*)(g_AO + base0 + d) = pack_half2(oacc[nf][0]*i0, oacc[nf][1]*i0);
        *(uint32_t*)(g_AO + base1 + d) = pack_half2(oacc[nf][2]*i1, oacc[nf][3]*i1);
    }
}

// ---------------- launch ----------------
extern "C" void kernel_launch(void* const* d_in, const int* in_sizes, int n_in,
                              void* d_out, int out_size)
{
    const float* inputs     = (const float*)d_in[0];
    const float* pos_emb    = (const float*)d_in[1];
    const float* full_input = (const float*)d_in[2];
    const float* u          = (const float*)d_in[3];
    const float* v          = (const float*)d_in[4];
    // d_in[5] = mask: unused (derived analytically)
    const float* W_kv   = (const float*)d_in[6];
    const float* b_kv   = (const float*)d_in[7];
    const float* W_q    = (const float*)d_in[8];
    const float* b_q    = (const float*)d_in[9];
    const float* W_pos  = (const float*)d_in[10];
    const float* b_pos  = (const float*)d_in[11];
    const float* W_proj = (const float*)d_in[12];
    const float* b_proj = (const float*)d_in[13];
    float* out = (float*)d_out;

    cudaFuncSetAttribute(k_gemm_projs, cudaFuncAttributeMaxDynamicSharedMemorySize, SM_BYTES);
    cudaFuncSetAttribute(k_gemm_pos,   cudaFuncAttributeMaxDynamicSharedMemorySize, SM_BYTES);
    cudaFuncSetAttribute(k_gemm_proj,  cudaFuncAttributeMaxDynamicSharedMemorySize, SM_BYTES);
    cudaFuncSetAttribute(k_attn_mma,   cudaFuncAttributeMaxDynamicSharedMemorySize, AT_BYTES);

    // 1. all conversions in one launch
    k_convert<<<NSPLIT_BLK + 5120, 256>>>(full_input, inputs, pos_emb,
                                          W_kv, W_q, W_pos, W_proj);
    // 2. merged KV + Q + R projection GEMMs (pipelined core)
    k_gemm_projs<<<1344, 256, SM_BYTES>>>(b_kv, b_q, b_pos, u, v);
    // 3. P quantized-shift store, dead tiles skipped
    k_gemm_pos<<<dim3(8, 4, 128), 256, SM_BYTES>>>();
    // 4. attention (single-sync pipelined K/V/P)
    k_attn_mma<<<dim3(4, 128), 256, AT_BYTES>>>();
    // 5. output projection (fused bias)
    k_gemm_proj<<<dim3(8, 32), 256, SM_BYTES>>>(b_proj, out);
}